// round 10
// baseline (speedup 1.0000x reference)
#include <cuda_runtime.h>
#include <cuda_fp16.h>
#include <cstdint>
#include <cstddef>

typedef __half  mha_h;
typedef __half2 mha_h2;

constexpr int MHA_B  = 4;
constexpr int MHA_S  = 2048;
constexpr int MHA_D  = 1024;
constexpr int MHA_H  = 16;
constexpr int MHA_DK = 64;

// ---------------- scratch ----------------
__device__ mha_h g_inh[(size_t)3*8192*1024];                     // input hi only
__device__ mha_h g_wh [(size_t)4*1024*1024];                     // weight hi
__device__ mha_h g_wl [(size_t)4*1024*1024];                     // weight lo
__device__ mha_h g_Qh[(size_t)8388608], g_Ql[(size_t)8388608];   // [bh][s][dk]
__device__ mha_h g_Kh[(size_t)8388608], g_Kl[(size_t)8388608];   // [bh][s][dk]
__device__ mha_h g_Vth[(size_t)8388608], g_Vtl[(size_t)8388608]; // [bh][dk][s]
__device__ mha_h g_Oh[(size_t)8388608];                          // [b][s][d] hi only

// ---------------- PTX helpers ----------------
__device__ __forceinline__ void mha_cpa16(uint32_t dst, const void* src) {
    asm volatile("cp.async.cg.shared.global [%0], [%1], 16;\n" :: "r"(dst), "l"(src));
}
__device__ __forceinline__ void mha_cp_commit() { asm volatile("cp.async.commit_group;\n"); }
template<int N> __device__ __forceinline__ void mha_cp_wait() {
    asm volatile("cp.async.wait_group %0;\n" :: "n"(N));
}
__device__ __forceinline__ void mha_ldsm4(uint32_t &r0, uint32_t &r1, uint32_t &r2,
                                          uint32_t &r3, uint32_t addr) {
    asm volatile("ldmatrix.sync.aligned.m8n8.x4.shared.b16 {%0,%1,%2,%3}, [%4];\n"
        : "=r"(r0),"=r"(r1),"=r"(r2),"=r"(r3) : "r"(addr));
}
__device__ __forceinline__ void mha_mma(float* d, const uint32_t* a, const uint32_t* b) {
    asm volatile("mma.sync.aligned.m16n8k16.row.col.f32.f16.f16.f32 "
      "{%0,%1,%2,%3}, {%4,%5,%6,%7}, {%8,%9}, {%0,%1,%2,%3};\n"
      : "+f"(d[0]),"+f"(d[1]),"+f"(d[2]),"+f"(d[3])
      : "r"(a[0]),"r"(a[1]),"r"(a[2]),"r"(a[3]),"r"(b[0]),"r"(b[1]));
}
__device__ __forceinline__ void mha_split2(float v0, float v1, mha_h2 &h2, mha_h2 &l2) {
    mha_h h0 = __float2half_rn(v0);
    mha_h h1 = __float2half_rn(v1);
    mha_h l0 = __float2half_rn(v0 - __half2float(h0));
    mha_h l1 = __float2half_rn(v1 - __half2float(h1));
    h2 = __halves2half2(h0, h1);
    l2 = __halves2half2(l0, l1);
}
__device__ __forceinline__ uint32_t mha_pack(float a, float b) {
    mha_h2 t = __floats2half2_rn(a, b);
    return *(uint32_t*)&t;
}

// ---------------- input/weight split ----------------
__global__ void mha_split_in3(const float* __restrict__ q, const float* __restrict__ k,
                              const float* __restrict__ v, mha_h* __restrict__ h) {
    const size_t NIN = (size_t)8192*1024;
    int seg = blockIdx.y;
    const float* x = (seg == 0) ? q : (seg == 1) ? k : v;
    size_t i = (size_t)blockIdx.x*blockDim.x + threadIdx.x;
    if (i >= NIN/4) return;
    float4 val = ((const float4*)x)[i];
    size_t o = (size_t)seg*(NIN/2) + 2*i;
    ((mha_h2*)h)[o]   = __floats2half2_rn(val.x, val.y);
    ((mha_h2*)h)[o+1] = __floats2half2_rn(val.z, val.w);
}
__global__ void mha_split_w4(const float* __restrict__ wq, const float* __restrict__ wk,
                             const float* __restrict__ wv, const float* __restrict__ wo,
                             mha_h* __restrict__ h, mha_h* __restrict__ l) {
    const size_t NW = (size_t)1024*1024;
    int seg = blockIdx.y;
    const float* x = (seg == 0) ? wq : (seg == 1) ? wk : (seg == 2) ? wv : wo;
    size_t i = (size_t)blockIdx.x*blockDim.x + threadIdx.x;
    if (i >= NW/4) return;
    float4 val = ((const float4*)x)[i];
    mha_h2 h0, l0, h1, l1;
    mha_split2(val.x, val.y, h0, l0);
    mha_split2(val.z, val.w, h1, l1);
    size_t o = (size_t)seg*(NW/2) + 2*i;
    ((mha_h2*)h)[o]   = h0;  ((mha_h2*)h)[o+1] = h1;
    ((mha_h2*)l)[o]   = l0;  ((mha_h2*)l)[o+1] = l1;
}

// ---------------- projection GEMM: C = Xh(M,K) @ (Wh+Wl)(N,K)^T -------------
constexpr int EP_QK_HEAD = 0;
constexpr int EP_V_HEADT = 1;
constexpr int EP_OUT     = 4;

__device__ __forceinline__ uint32_t mha_swz(int row, int kc) {
    return (uint32_t)(row*64 + ((kc ^ ((row >> 1) & 3)) << 4));
}

template<int BM, int BN>
__device__ __forceinline__ void mha_issue(
    uint32_t s0, int tid, int bm, int bn, int kk, int K,
    const mha_h* pAh, const mha_h* pBh, const mha_h* pBl)
{
    constexpr int ABYTES = BM * 64;
    constexpr int BBYTES = BN * 64;
    #pragma unroll
    for (int c = tid; c < BM*4; c += 256) {
        int row = c >> 2, kc = c & 3;
        uint32_t off = mha_swz(row, kc);
        size_t g = (size_t)(bm + row) * K + kk + kc*8;
        mha_cpa16(s0 + off, pAh + g);
    }
    #pragma unroll
    for (int c = tid; c < BN*4; c += 256) {
        int row = c >> 2, kc = c & 3;
        uint32_t off = mha_swz(row, kc);
        size_t g = (size_t)(bn + row) * K + kk + kc*8;
        mha_cpa16(s0 + ABYTES + off,          pBh + g);
        mha_cpa16(s0 + ABYTES + BBYTES + off, pBl + g);
    }
}

template<int BM, int BN, int WSM, int WSN, int MODE>
__global__ void __launch_bounds__(256, 2) mha_gemm(
    const mha_h* __restrict__ Ah,
    const mha_h* __restrict__ Bh, const mha_h* __restrict__ Bl,
    const float* __restrict__ bias,
    float* __restrict__ Cf, mha_h* __restrict__ Ch, mha_h* __restrict__ Cl,
    int M, int N, int K)
{
    constexpr int WM = BM / WSM, WN = BN / WSN;
    constexpr int MT = WM / 16,  NT = WN / 8;
    constexpr int ABYTES = BM * 64;
    constexpr int BBYTES = BN * 64;
    constexpr int STAGE  = ABYTES + 2*BBYTES;

    extern __shared__ char smem[];
    uint32_t sbase = (uint32_t)__cvta_generic_to_shared(smem);

    int tid  = threadIdx.x;
    int warp = tid >> 5, lane = tid & 31;
    int wm = warp / WSN, wn = warp % WSN;
    int bm = blockIdx.y * BM, bn = blockIdx.x * BN;

    float acc[MT][NT][4];
    #pragma unroll
    for (int i = 0; i < MT; i++)
        #pragma unroll
        for (int j = 0; j < NT; j++)
            #pragma unroll
            for (int r = 0; r < 4; r++) acc[i][j][r] = 0.f;

    int ITERS = K / 32;
    mha_issue<BM,BN>(sbase, tid, bm, bn, 0, K, Ah, Bh, Bl);
    mha_cp_commit();

    for (int it = 0; it < ITERS; it++) {
        if (it + 1 < ITERS)
            mha_issue<BM,BN>(sbase + ((it+1)&1)*STAGE, tid, bm, bn, (it+1)*32, K,
                             Ah, Bh, Bl);
        mha_cp_commit();
        mha_cp_wait<1>(); __syncthreads();

        uint32_t sAh0 = sbase + (it&1)*STAGE;
        uint32_t sBh0 = sAh0 + ABYTES;
        uint32_t sBl0 = sBh0 + BBYTES;

        #pragma unroll
        for (int ks = 0; ks < 2; ks++) {
            int kc0 = ks * 2;
            uint32_t fah[MT][4], fbh[NT][2], fbl[NT][2];
            #pragma unroll
            for (int mt = 0; mt < MT; mt++) {
                int r  = wm*WM + mt*16 + (lane & 15);
                int kc = kc0 + (lane >> 4);
                uint32_t off = mha_swz(r, kc);
                mha_ldsm4(fah[mt][0],fah[mt][1],fah[mt][2],fah[mt][3], sAh0 + off);
            }
            #pragma unroll
            for (int g = 0; g < NT/2; g++) {
                int r  = wn*WN + g*16 + (lane & 15);
                int kc = kc0 + (lane >> 4);
                uint32_t off = mha_swz(r, kc);
                uint32_t t0,t1,t2,t3;
                mha_ldsm4(t0,t1,t2,t3, sBh0 + off);
                fbh[2*g][0]=t0; fbh[2*g][1]=t2; fbh[2*g+1][0]=t1; fbh[2*g+1][1]=t3;
                mha_ldsm4(t0,t1,t2,t3, sBl0 + off);
                fbl[2*g][0]=t0; fbl[2*g][1]=t2; fbl[2*g+1][0]=t1; fbl[2*g+1][1]=t3;
            }
            #pragma unroll
            for (int mt = 0; mt < MT; mt++)
                #pragma unroll
                for (int nt = 0; nt < NT; nt++) {
                    mha_mma(acc[mt][nt], fah[mt], fbh[nt]);
                    mha_mma(acc[mt][nt], fah[mt], fbl[nt]);
                }
        }
        __syncthreads();
    }

    #pragma unroll
    for (int mt = 0; mt < MT; mt++)
        #pragma unroll
        for (int nt = 0; nt < NT; nt++) {
            int r0 = bm + wm*WM + mt*16 + (lane >> 2);
            int c0 = bn + wn*WN + nt*8  + (lane & 3)*2;
            #pragma unroll
            for (int half = 0; half < 2; half++) {
                int r = r0 + half*8;
                float v0 = acc[mt][nt][2*half], v1 = acc[mt][nt][2*half+1];
                if (MODE == EP_OUT) {
                    float2 o = make_float2(v0 + bias[c0], v1 + bias[c0+1]);
                    *(float2*)(Cf + (size_t)r*N + c0) = o;
                } else if (MODE == EP_QK_HEAD) {
                    v0 += bias[c0]; v1 += bias[c0+1];
                    int b = r >> 11, s = r & (MHA_S-1);
                    int h = c0 >> 6, dk = c0 & 63;
                    size_t idx = (((size_t)(b*MHA_H + h))*MHA_S + s)*MHA_DK + dk;
                    mha_h2 h2, l2; mha_split2(v0, v1, h2, l2);
                    *(mha_h2*)(Ch + idx) = h2;
                    *(mha_h2*)(Cl + idx) = l2;
                } else { // EP_V_HEADT
                    v0 += bias[c0]; v1 += bias[c0+1];
                    int b = r >> 11, s = r & (MHA_S-1);
                    int h = c0 >> 6, dk = c0 & 63;
                    size_t idx = (((size_t)(b*MHA_H + h))*MHA_DK + dk)*MHA_S + s;
                    mha_h2 h2, l2; mha_split2(v0, v1, h2, l2);
                    Ch[idx] = __low2half(h2);  Ch[idx + MHA_S] = __high2half(h2);
                    Cl[idx] = __low2half(l2);  Cl[idx + MHA_S] = __high2half(l2);
                }
            }
        }
}

// =================== fused flash attention v2 (BM=256, MT=2) =================
// One CTA = 256 q-rows. 8 warps x 32 rows (2 m16 tiles). K/V fragments
// amortized over 2x the MMAs vs v1. Q-hi frags in regs; Q-lo re-read from smem.
constexpr int FS_QB    = 256*128;              // Q hi (or lo) 32KB
constexpr int FS_KB    = 128*128;              // K half tile 16KB
constexpr int FS_VB    = 64*256;               // V half tile 16KB
constexpr int FS_STAGE = 2*FS_KB + 2*FS_VB;    // 64KB
constexpr int FS_SMEM  = 2*FS_QB + 2*FS_STAGE; // 192KB

__device__ __forceinline__ uint32_t fs_swzk(int row, int c) {
    return (uint32_t)(row*128 + ((c ^ (row & 7)) << 4));
}
__device__ __forceinline__ uint32_t fs_swzv(int row, int c) {
    return (uint32_t)(row*256 + ((c ^ (row & 7)) << 4));
}

__device__ __forceinline__ void fs_loadQ(uint32_t qb, int tid, int bh, int q0,
                                         const mha_h* Qh, const mha_h* Ql) {
    #pragma unroll
    for (int i = tid; i < 2048; i += 256) {
        int row = i >> 3, c = i & 7;
        uint32_t off = fs_swzk(row, c);
        size_t g = ((size_t)bh*MHA_S + q0 + row)*MHA_DK + c*8;
        mha_cpa16(qb + off,         Qh + g);
        mha_cpa16(qb + FS_QB + off, Ql + g);
    }
}
__device__ __forceinline__ void fs_loadK_hi(uint32_t sb, int tid, int bh, int t,
                                            const mha_h* Kh) {
    #pragma unroll
    for (int i = tid; i < 1024; i += 256) {
        int row = i >> 3, c = i & 7;
        uint32_t off = fs_swzk(row, c);
        size_t g = ((size_t)bh*MHA_S + t*128 + row)*MHA_DK + c*8;
        mha_cpa16(sb + off, Kh + g);
    }
}
__device__ __forceinline__ void fs_loadK(uint32_t sb, int tid, int bh, int t,
                                         const mha_h* Kh, const mha_h* Kl) {
    #pragma unroll
    for (int i = tid; i < 1024; i += 256) {
        int row = i >> 3, c = i & 7;
        uint32_t off = fs_swzk(row, c);
        size_t g = ((size_t)bh*MHA_S + t*128 + row)*MHA_DK + c*8;
        mha_cpa16(sb + off,         Kh + g);
        mha_cpa16(sb + FS_KB + off, Kl + g);
    }
}
__device__ __forceinline__ void fs_loadV(uint32_t sb, int tid, int bh, int t,
                                         const mha_h* Vh, const mha_h* Vl) {
    #pragma unroll
    for (int i = tid; i < 1024; i += 256) {
        int row = i >> 4, c = i & 15;
        uint32_t off = fs_swzv(row, c);
        size_t g = ((size_t)bh*MHA_DK + row)*MHA_S + t*128 + c*8;
        mha_cpa16(sb + 2*FS_KB + off,         Vh + g);
        mha_cpa16(sb + 2*FS_KB + FS_VB + off, Vl + g);
    }
}

__global__ void __launch_bounds__(256) mha_flash(
    const mha_h* __restrict__ Qh, const mha_h* __restrict__ Ql,
    const mha_h* __restrict__ Kh, const mha_h* __restrict__ Kl,
    const mha_h* __restrict__ Vh, const mha_h* __restrict__ Vl,
    float* __restrict__ attn, mha_h* __restrict__ Oh)
{
    extern __shared__ char smem[];
    uint32_t sbase = (uint32_t)__cvta_generic_to_shared(smem);
    uint32_t qb  = sbase;                // Q hi; Q lo at qb + FS_QB
    uint32_t stg = sbase + 2*FS_QB;

    int tid = threadIdx.x;
    int warp = tid >> 5, lane = tid & 31;
    int bh = blockIdx.y;
    int q0 = blockIdx.x * 256;

    uint32_t qfh[2][4][4];               // Q hi frags: [mt][j][4]
    float s[2][2] = {{0.f,0.f},{0.f,0.f}};

    // ---- pass 1: hi-only fp16 scores -> row sums of exp(S) ----
    fs_loadQ(qb, tid, bh, q0, Qh, Ql);
    fs_loadK_hi(stg, tid, bh, 0, Kh);
    mha_cp_commit();

    for (int t = 0; t < 16; t++) {
        if (t + 1 < 16) fs_loadK_hi(stg + ((t+1)&1)*FS_STAGE, tid, bh, t+1, Kh);
        mha_cp_commit();
        mha_cp_wait<1>(); __syncthreads();

        if (t == 0) {
            #pragma unroll
            for (int mt = 0; mt < 2; mt++)
                #pragma unroll
                for (int j = 0; j < 4; j++) {
                    int r = warp*32 + mt*16 + (lane & 15);
                    int c = 2*j + (lane >> 4);
                    uint32_t off = fs_swzk(r, c);
                    mha_ldsm4(qfh[mt][j][0],qfh[mt][j][1],qfh[mt][j][2],qfh[mt][j][3],
                              qb + off);
                }
        }

        uint32_t kb = stg + (t&1)*FS_STAGE;
        #pragma unroll
        for (int hf = 0; hf < 2; hf++) {
            float acc[2][8][4];
            #pragma unroll
            for (int mt = 0; mt < 2; mt++)
                #pragma unroll
                for (int nt = 0; nt < 8; nt++)
                    #pragma unroll
                    for (int r = 0; r < 4; r++) acc[mt][nt][r] = 0.f;
            #pragma unroll
            for (int j = 0; j < 4; j++) {
                uint32_t kh[8][2];
                #pragma unroll
                for (int g = 0; g < 4; g++) {
                    int r = hf*64 + g*16 + (lane & 15);
                    int c = 2*j + (lane >> 4);
                    uint32_t off = fs_swzk(r, c);
                    uint32_t t0,t1,t2,t3;
                    mha_ldsm4(t0,t1,t2,t3, kb + off);
                    kh[2*g][0]=t0; kh[2*g][1]=t2; kh[2*g+1][0]=t1; kh[2*g+1][1]=t3;
                }
                #pragma unroll
                for (int mt = 0; mt < 2; mt++)
                    #pragma unroll
                    for (int nt = 0; nt < 8; nt++)
                        mha_mma(acc[mt][nt], qfh[mt][j], kh[nt]);
            }
            #pragma unroll
            for (int mt = 0; mt < 2; mt++)
                #pragma unroll
                for (int nt = 0; nt < 8; nt++) {
                    s[mt][0] += __expf(acc[mt][nt][0]*0.125f) + __expf(acc[mt][nt][1]*0.125f);
                    s[mt][1] += __expf(acc[mt][nt][2]*0.125f) + __expf(acc[mt][nt][3]*0.125f);
                }
        }
        __syncthreads();
    }

    float inv[2][2];
    #pragma unroll
    for (int mt = 0; mt < 2; mt++)
        #pragma unroll
        for (int hh = 0; hh < 2; hh++) {
            float v = s[mt][hh];
            v += __shfl_xor_sync(0xffffffffu, v, 1);
            v += __shfl_xor_sync(0xffffffffu, v, 2);
            inv[mt][hh] = 1.f / v;
        }

    float oacc[2][8][4];
    #pragma unroll
    for (int mt = 0; mt < 2; mt++)
        #pragma unroll
        for (int nd = 0; nd < 8; nd++)
            #pragma unroll
            for (int r = 0; r < 4; r++) oacc[mt][nd][r] = 0.f;

    // ---- pass 2: 3-term scores, P = exp(S)*inv, write P, O += P(hi) * V ----
    fs_loadK(stg, tid, bh, 0, Kh, Kl);
    fs_loadV(stg, tid, bh, 0, Vh, Vl);
    mha_cp_commit();

    int qrow[2];
    qrow[0] = q0 + warp*32 + (lane >> 2);
    qrow[1] = qrow[0] + 16;

    for (int t = 0; t < 16; t++) {
        if (t + 1 < 16) {
            fs_loadK(stg + ((t+1)&1)*FS_STAGE, tid, bh, t+1, Kh, Kl);
            fs_loadV(stg + ((t+1)&1)*FS_STAGE, tid, bh, t+1, Vh, Vl);
        }
        mha_cp_commit();
        mha_cp_wait<1>(); __syncthreads();

        uint32_t kb = stg + (t&1)*FS_STAGE;
        #pragma unroll
        for (int hf = 0; hf < 2; hf++) {
            float acc[2][8][4];
            #pragma unroll
            for (int mt = 0; mt < 2; mt++)
                #pragma unroll
                for (int nt = 0; nt < 8; nt++)
                    #pragma unroll
                    for (int r = 0; r < 4; r++) acc[mt][nt][r] = 0.f;

            #pragma unroll
            for (int j = 0; j < 4; j++) {
                uint32_t kh[8][2], kl[8][2];
                #pragma unroll
                for (int g = 0; g < 4; g++) {
                    int r = hf*64 + g*16 + (lane & 15);
                    int c = 2*j + (lane >> 4);
                    uint32_t off = fs_swzk(r, c);
                    uint32_t t0,t1,t2,t3;
                    mha_ldsm4(t0,t1,t2,t3, kb + off);
                    kh[2*g][0]=t0; kh[2*g][1]=t2; kh[2*g+1][0]=t1; kh[2*g+1][1]=t3;
                    mha_ldsm4(t0,t1,t2,t3, kb + FS_KB + off);
                    kl[2*g][0]=t0; kl[2*g][1]=t2; kl[2*g+1][0]=t1; kl[2*g+1][1]=t3;
                }
                #pragma unroll
                for (int mt = 0; mt < 2; mt++) {
                    // Q-lo fragment from smem (reused NT times right here)
                    uint32_t ql4[4];
                    {
                        int r = warp*32 + mt*16 + (lane & 15);
                        int c = 2*j + (lane >> 4);
                        uint32_t off = fs_swzk(r, c);
                        mha_ldsm4(ql4[0],ql4[1],ql4[2],ql4[3], qb + FS_QB + off);
                    }
                    #pragma unroll
                    for (int nt = 0; nt < 8; nt++) {
                        mha_mma(acc[mt][nt], qfh[mt][j], kh[nt]);
                        mha_mma(acc[mt][nt], qfh[mt][j], kl[nt]);
                        mha_mma(acc[mt][nt], ql4,        kh[nt]);
                    }
                }
            }

            // softmax-normalize + write P
            #pragma unroll
            for (int mt = 0; mt < 2; mt++) {
                #pragma unroll
                for (int nt = 0; nt < 8; nt++) {
                    acc[mt][nt][0] = __expf(acc[mt][nt][0]*0.125f)*inv[mt][0];
                    acc[mt][nt][1] = __expf(acc[mt][nt][1]*0.125f)*inv[mt][0];
                    acc[mt][nt][2] = __expf(acc[mt][nt][2]*0.125f)*inv[mt][1];
                    acc[mt][nt][3] = __expf(acc[mt][nt][3]*0.125f)*inv[mt][1];
                }
                size_t rb0 = ((size_t)bh*MHA_S + qrow[mt])    *MHA_S + t*128 + hf*64 + (lane&3)*2;
                size_t rb1 = ((size_t)bh*MHA_S + qrow[mt] + 8)*MHA_S + t*128 + hf*64 + (lane&3)*2;
                #pragma unroll
                for (int nt = 0; nt < 8; nt++) {
                    *(float2*)(attn + rb0 + nt*8) = make_float2(acc[mt][nt][0], acc[mt][nt][1]);
                    *(float2*)(attn + rb1 + nt*8) = make_float2(acc[mt][nt][2], acc[mt][nt][3]);
                }
            }

            // PV accumulate (V frags shared across both m-tiles)
            #pragma unroll
            for (int kk = 0; kk < 4; kk++) {
                uint32_t vbh[8][2], vbl[8][2];
                #pragma unroll
                for (int g = 0; g < 4; g++) {
                    int r = g*16 + (lane & 15);
                    int c = 2*(hf*4 + kk) + (lane >> 4);
                    uint32_t off = fs_swzv(r, c);
                    uint32_t t0,t1,t2,t3;
                    mha_ldsm4(t0,t1,t2,t3, kb + 2*FS_KB + off);
                    vbh[2*g][0]=t0; vbh[2*g][1]=t2; vbh[2*g+1][0]=t1; vbh[2*g+1][1]=t3;
                    mha_ldsm4(t0,t1,t2,t3, kb + 2*FS_KB + FS_VB + off);
                    vbl[2*g][0]=t0; vbl[2*g][1]=t2; vbl[2*g+1][0]=t1; vbl[2*g+1][1]=t3;
                }
                #pragma unroll
                for (int mt = 0; mt < 2; mt++) {
                    uint32_t pah[4];
                    pah[0] = mha_pack(acc[mt][2*kk][0],   acc[mt][2*kk][1]);
                    pah[1] = mha_pack(acc[mt][2*kk][2],   acc[mt][2*kk][3]);
                    pah[2] = mha_pack(acc[mt][2*kk+1][0], acc[mt][2*kk+1][1]);
                    pah[3] = mha_pack(acc[mt][2*kk+1][2], acc[mt][2*kk+1][3]);
                    #pragma unroll
                    for (int nd = 0; nd < 8; nd++) {
                        mha_mma(oacc[mt][nd], pah, vbh[nd]);
                        mha_mma(oacc[mt][nd], pah, vbl[nd]);
                    }
                }
            }
        }
        __syncthreads();
    }

    // ---- O epilogue: hi-only fp16 [b][s][d] ----
    int b = bh >> 4, h = bh & 15;
    #pragma unroll
    for (int mt = 0; mt < 2; mt++)
        #pragma unroll
        for (int nd = 0; nd < 8; nd++) {
            int dk = nd*8 + (lane & 3)*2;
            size_t i0 = ((size_t)(b*MHA_S + qrow[mt]))    *MHA_D + h*MHA_DK + dk;
            size_t i1 = ((size_t)(b*MHA_S + qrow[mt] + 8))*MHA_D + h*MHA_DK + dk;
            *(mha_h2*)(Oh + i0) = __floats2half2_rn(oacc[mt][nd][0], oacc[mt][nd][1]);
            *(mha_h2*)(Oh + i1) = __floats2half2_rn(oacc[mt][nd][2], oacc[mt][nd][3]);
        }
}

// ---------------- host ----------------
extern "C" void kernel_launch(void* const* d_in, const int* in_sizes, int n_in,
                              void* d_out, int out_size)
{
    (void)in_sizes; (void)n_in; (void)out_size;
    const float* q  = (const float*)d_in[0];
    const float* k  = (const float*)d_in[1];
    const float* v  = (const float*)d_in[2];
    const float* wq = (const float*)d_in[3];
    const float* bq = (const float*)d_in[4];
    const float* wk = (const float*)d_in[5];
    const float* bk = (const float*)d_in[6];
    const float* wv = (const float*)d_in[7];
    const float* bv = (const float*)d_in[8];
    const float* wo = (const float*)d_in[9];
    const float* bo = (const float*)d_in[10];

    float* out  = (float*)d_out;
    float* attn = out + (size_t)MHA_B * MHA_S * MHA_D;

    mha_h *inh, *wh, *wl, *Qh, *Ql, *Kh, *Kl, *Vth, *Vtl, *Oh;
    cudaGetSymbolAddress((void**)&inh, g_inh);
    cudaGetSymbolAddress((void**)&wh,  g_wh);
    cudaGetSymbolAddress((void**)&wl,  g_wl);
    cudaGetSymbolAddress((void**)&Qh,  g_Qh);
    cudaGetSymbolAddress((void**)&Ql,  g_Ql);
    cudaGetSymbolAddress((void**)&Kh,  g_Kh);
    cudaGetSymbolAddress((void**)&Kl,  g_Kl);
    cudaGetSymbolAddress((void**)&Vth, g_Vth);
    cudaGetSymbolAddress((void**)&Vtl, g_Vtl);
    cudaGetSymbolAddress((void**)&Oh,  g_Oh);

    const size_t NIN = (size_t)8192*1024;
    const size_t NW  = (size_t)1024*1024;

    mha_split_in3<<<dim3((unsigned)(NIN/4/256), 3), 256>>>(q, k, v, inh);
    mha_split_w4 <<<dim3((unsigned)(NW/4/256),  4), 256>>>(wq, wk, wv, wo, wh, wl);

    auto gq  = mha_gemm<128,128,2,4,EP_QK_HEAD>;
    auto gv2 = mha_gemm<128,128,2,4,EP_V_HEADT>;
    auto gou = mha_gemm<128,128,2,4,EP_OUT>;

    const int SM128 = 2 * (128*64 + 2*128*64);   // 49152 B
    cudaFuncSetAttribute(gq,  cudaFuncAttributeMaxDynamicSharedMemorySize, SM128);
    cudaFuncSetAttribute(gv2, cudaFuncAttributeMaxDynamicSharedMemorySize, SM128);
    cudaFuncSetAttribute(gou, cudaFuncAttributeMaxDynamicSharedMemorySize, SM128);
    cudaFuncSetAttribute(mha_flash, cudaFuncAttributeMaxDynamicSharedMemorySize, FS_SMEM);

    dim3 t(256);

    dim3 gproj(1024/128, 8192/128, 1);
    gq <<<gproj, t, SM128>>>(inh,         wh,        wl,        bq,
                             nullptr, Qh, Ql, 8192, 1024, 1024);
    gq <<<gproj, t, SM128>>>(inh + NIN,   wh + NW,   wl + NW,   bk,
                             nullptr, Kh, Kl, 8192, 1024, 1024);
    gv2<<<gproj, t, SM128>>>(inh + 2*NIN, wh + 2*NW, wl + 2*NW, bv,
                             nullptr, Vth, Vtl, 8192, 1024, 1024);

    dim3 gf(2048/256, MHA_B*MHA_H);
    mha_flash<<<gf, t, FS_SMEM>>>(Qh, Ql, Kh, Kl, Vth, Vtl, attn, Oh);

    gou<<<gproj, t, SM128>>>(Oh, wh + 3*NW, wl + 3*NW, bo,
                             out, nullptr, nullptr, 8192, 1024, 1024);
}

// round 11
// speedup vs baseline: 1.2586x; 1.2586x over previous
#include <cuda_runtime.h>
#include <cuda_fp16.h>
#include <cstdint>
#include <cstddef>

typedef __half  mha_h;
typedef __half2 mha_h2;

constexpr int MHA_B  = 4;
constexpr int MHA_S  = 2048;
constexpr int MHA_D  = 1024;
constexpr int MHA_H  = 16;
constexpr int MHA_DK = 64;

// ---------------- scratch ----------------
__device__ mha_h g_inh[(size_t)3*8192*1024];                     // input hi only
__device__ mha_h g_wh [(size_t)4*1024*1024];                     // weight hi
__device__ mha_h g_wl [(size_t)4*1024*1024];                     // weight lo
__device__ mha_h g_Qh[(size_t)8388608];                          // [bh][s][dk] hi
__device__ mha_h g_Kh[(size_t)8388608], g_Kl[(size_t)8388608];   // [bh][s][dk]
__device__ mha_h g_Vth[(size_t)8388608];                         // [bh][dk][s] hi
__device__ mha_h g_Oh[(size_t)8388608];                          // [b][s][d] hi

// ---------------- PTX helpers ----------------
__device__ __forceinline__ void mha_cpa16(uint32_t dst, const void* src) {
    asm volatile("cp.async.cg.shared.global [%0], [%1], 16;\n" :: "r"(dst), "l"(src));
}
__device__ __forceinline__ void mha_cp_commit() { asm volatile("cp.async.commit_group;\n"); }
template<int N> __device__ __forceinline__ void mha_cp_wait() {
    asm volatile("cp.async.wait_group %0;\n" :: "n"(N));
}
__device__ __forceinline__ void mha_ldsm4(uint32_t &r0, uint32_t &r1, uint32_t &r2,
                                          uint32_t &r3, uint32_t addr) {
    asm volatile("ldmatrix.sync.aligned.m8n8.x4.shared.b16 {%0,%1,%2,%3}, [%4];\n"
        : "=r"(r0),"=r"(r1),"=r"(r2),"=r"(r3) : "r"(addr));
}
__device__ __forceinline__ void mha_mma(float* d, const uint32_t* a, const uint32_t* b) {
    asm volatile("mma.sync.aligned.m16n8k16.row.col.f32.f16.f16.f32 "
      "{%0,%1,%2,%3}, {%4,%5,%6,%7}, {%8,%9}, {%0,%1,%2,%3};\n"
      : "+f"(d[0]),"+f"(d[1]),"+f"(d[2]),"+f"(d[3])
      : "r"(a[0]),"r"(a[1]),"r"(a[2]),"r"(a[3]),"r"(b[0]),"r"(b[1]));
}
__device__ __forceinline__ void mha_split2(float v0, float v1, mha_h2 &h2, mha_h2 &l2) {
    mha_h h0 = __float2half_rn(v0);
    mha_h h1 = __float2half_rn(v1);
    mha_h l0 = __float2half_rn(v0 - __half2float(h0));
    mha_h l1 = __float2half_rn(v1 - __half2float(h1));
    h2 = __halves2half2(h0, h1);
    l2 = __halves2half2(l0, l1);
}
__device__ __forceinline__ uint32_t mha_pack(float a, float b) {
    mha_h2 t = __floats2half2_rn(a, b);
    return *(uint32_t*)&t;
}

// ---------------- input/weight split ----------------
__global__ void mha_split_in3(const float* __restrict__ q, const float* __restrict__ k,
                              const float* __restrict__ v, mha_h* __restrict__ h) {
    const size_t NIN = (size_t)8192*1024;
    int seg = blockIdx.y;
    const float* x = (seg == 0) ? q : (seg == 1) ? k : v;
    size_t i = (size_t)blockIdx.x*blockDim.x + threadIdx.x;
    if (i >= NIN/4) return;
    float4 val = ((const float4*)x)[i];
    size_t o = (size_t)seg*(NIN/2) + 2*i;
    ((mha_h2*)h)[o]   = __floats2half2_rn(val.x, val.y);
    ((mha_h2*)h)[o+1] = __floats2half2_rn(val.z, val.w);
}
__global__ void mha_split_w4(const float* __restrict__ wq, const float* __restrict__ wk,
                             const float* __restrict__ wv, const float* __restrict__ wo,
                             mha_h* __restrict__ h, mha_h* __restrict__ l) {
    const size_t NW = (size_t)1024*1024;
    int seg = blockIdx.y;
    const float* x = (seg == 0) ? wq : (seg == 1) ? wk : (seg == 2) ? wv : wo;
    size_t i = (size_t)blockIdx.x*blockDim.x + threadIdx.x;
    if (i >= NW/4) return;
    float4 val = ((const float4*)x)[i];
    mha_h2 h0, l0, h1, l1;
    mha_split2(val.x, val.y, h0, l0);
    mha_split2(val.z, val.w, h1, l1);
    size_t o = (size_t)seg*(NW/2) + 2*i;
    ((mha_h2*)h)[o]   = h0;  ((mha_h2*)h)[o+1] = h1;
    ((mha_h2*)l)[o]   = l0;  ((mha_h2*)l)[o+1] = l1;
}

// ---------------- projection GEMM: C = Xh(M,K) @ (Wh+Wl)(N,K)^T -------------
constexpr int EP_Q_HEAD  = 0;   // head-major, hi only
constexpr int EP_K_HEAD  = 1;   // head-major, hi+lo
constexpr int EP_V_HEADT = 2;   // transposed head-major, hi only
constexpr int EP_OUT     = 4;   // fp32 + bias

__device__ __forceinline__ uint32_t mha_swz(int row, int kc) {
    return (uint32_t)(row*64 + ((kc ^ ((row >> 1) & 3)) << 4));
}

template<int BM, int BN>
__device__ __forceinline__ void mha_issue(
    uint32_t s0, int tid, int bm, int bn, int kk, int K,
    const mha_h* pAh, const mha_h* pBh, const mha_h* pBl)
{
    constexpr int ABYTES = BM * 64;
    constexpr int BBYTES = BN * 64;
    #pragma unroll
    for (int c = tid; c < BM*4; c += 256) {
        int row = c >> 2, kc = c & 3;
        uint32_t off = mha_swz(row, kc);
        size_t g = (size_t)(bm + row) * K + kk + kc*8;
        mha_cpa16(s0 + off, pAh + g);
    }
    #pragma unroll
    for (int c = tid; c < BN*4; c += 256) {
        int row = c >> 2, kc = c & 3;
        uint32_t off = mha_swz(row, kc);
        size_t g = (size_t)(bn + row) * K + kk + kc*8;
        mha_cpa16(s0 + ABYTES + off,          pBh + g);
        mha_cpa16(s0 + ABYTES + BBYTES + off, pBl + g);
    }
}

template<int BM, int BN, int WSM, int WSN, int MODE>
__global__ void __launch_bounds__(256, 2) mha_gemm(
    const mha_h* __restrict__ Ah,
    const mha_h* __restrict__ Bh, const mha_h* __restrict__ Bl,
    const float* __restrict__ bias,
    float* __restrict__ Cf, mha_h* __restrict__ Ch, mha_h* __restrict__ Cl,
    int M, int N, int K)
{
    constexpr int WM = BM / WSM, WN = BN / WSN;
    constexpr int MT = WM / 16,  NT = WN / 8;
    constexpr int ABYTES = BM * 64;
    constexpr int BBYTES = BN * 64;
    constexpr int STAGE  = ABYTES + 2*BBYTES;

    extern __shared__ char smem[];
    uint32_t sbase = (uint32_t)__cvta_generic_to_shared(smem);

    int tid  = threadIdx.x;
    int warp = tid >> 5, lane = tid & 31;
    int wm = warp / WSN, wn = warp % WSN;
    int bm = blockIdx.y * BM, bn = blockIdx.x * BN;

    float acc[MT][NT][4];
    #pragma unroll
    for (int i = 0; i < MT; i++)
        #pragma unroll
        for (int j = 0; j < NT; j++)
            #pragma unroll
            for (int r = 0; r < 4; r++) acc[i][j][r] = 0.f;

    int ITERS = K / 32;
    mha_issue<BM,BN>(sbase, tid, bm, bn, 0, K, Ah, Bh, Bl);
    mha_cp_commit();

    for (int it = 0; it < ITERS; it++) {
        if (it + 1 < ITERS)
            mha_issue<BM,BN>(sbase + ((it+1)&1)*STAGE, tid, bm, bn, (it+1)*32, K,
                             Ah, Bh, Bl);
        mha_cp_commit();
        mha_cp_wait<1>(); __syncthreads();

        uint32_t sAh0 = sbase + (it&1)*STAGE;
        uint32_t sBh0 = sAh0 + ABYTES;
        uint32_t sBl0 = sBh0 + BBYTES;

        #pragma unroll
        for (int ks = 0; ks < 2; ks++) {
            int kc0 = ks * 2;
            uint32_t fah[MT][4], fbh[NT][2], fbl[NT][2];
            #pragma unroll
            for (int mt = 0; mt < MT; mt++) {
                int r  = wm*WM + mt*16 + (lane & 15);
                int kc = kc0 + (lane >> 4);
                uint32_t off = mha_swz(r, kc);
                mha_ldsm4(fah[mt][0],fah[mt][1],fah[mt][2],fah[mt][3], sAh0 + off);
            }
            #pragma unroll
            for (int g = 0; g < NT/2; g++) {
                int r  = wn*WN + g*16 + (lane & 15);
                int kc = kc0 + (lane >> 4);
                uint32_t off = mha_swz(r, kc);
                uint32_t t0,t1,t2,t3;
                mha_ldsm4(t0,t1,t2,t3, sBh0 + off);
                fbh[2*g][0]=t0; fbh[2*g][1]=t2; fbh[2*g+1][0]=t1; fbh[2*g+1][1]=t3;
                mha_ldsm4(t0,t1,t2,t3, sBl0 + off);
                fbl[2*g][0]=t0; fbl[2*g][1]=t2; fbl[2*g+1][0]=t1; fbl[2*g+1][1]=t3;
            }
            #pragma unroll
            for (int mt = 0; mt < MT; mt++)
                #pragma unroll
                for (int nt = 0; nt < NT; nt++) {
                    mha_mma(acc[mt][nt], fah[mt], fbh[nt]);
                    mha_mma(acc[mt][nt], fah[mt], fbl[nt]);
                }
        }
        __syncthreads();
    }

    #pragma unroll
    for (int mt = 0; mt < MT; mt++)
        #pragma unroll
        for (int nt = 0; nt < NT; nt++) {
            int r0 = bm + wm*WM + mt*16 + (lane >> 2);
            int c0 = bn + wn*WN + nt*8  + (lane & 3)*2;
            #pragma unroll
            for (int half = 0; half < 2; half++) {
                int r = r0 + half*8;
                float v0 = acc[mt][nt][2*half], v1 = acc[mt][nt][2*half+1];
                if (MODE == EP_OUT) {
                    float2 o = make_float2(v0 + bias[c0], v1 + bias[c0+1]);
                    *(float2*)(Cf + (size_t)r*N + c0) = o;
                } else if (MODE == EP_Q_HEAD) {
                    v0 += bias[c0]; v1 += bias[c0+1];
                    int b = r >> 11, s = r & (MHA_S-1);
                    int h = c0 >> 6, dk = c0 & 63;
                    size_t idx = (((size_t)(b*MHA_H + h))*MHA_S + s)*MHA_DK + dk;
                    *(mha_h2*)(Ch + idx) = __floats2half2_rn(v0, v1);
                } else if (MODE == EP_K_HEAD) {
                    v0 += bias[c0]; v1 += bias[c0+1];
                    int b = r >> 11, s = r & (MHA_S-1);
                    int h = c0 >> 6, dk = c0 & 63;
                    size_t idx = (((size_t)(b*MHA_H + h))*MHA_S + s)*MHA_DK + dk;
                    mha_h2 h2, l2; mha_split2(v0, v1, h2, l2);
                    *(mha_h2*)(Ch + idx) = h2;
                    *(mha_h2*)(Cl + idx) = l2;
                } else { // EP_V_HEADT (hi only)
                    v0 += bias[c0]; v1 += bias[c0+1];
                    int b = r >> 11, s = r & (MHA_S-1);
                    int h = c0 >> 6, dk = c0 & 63;
                    size_t idx = (((size_t)(b*MHA_H + h))*MHA_DK + dk)*MHA_S + s;
                    Ch[idx]         = __float2half_rn(v0);
                    Ch[idx + MHA_S] = __float2half_rn(v1);
                }
            }
        }
}

// =================== fused flash attention (R8 shape, fewer terms) ===========
// Pass 1: qh·kh scores -> row sums of exp(S).
// Pass 2: 2-term scores (qh·kh + qh·kl), P = exp(S)*inv, write P, O += P·Vh.
constexpr int FS_QB    = 128*128;              // Q hi 16KB
constexpr int FS_KB    = 128*128;              // K half 16KB
constexpr int FS_VB    = 64*256;               // V hi 16KB
constexpr int FS_STAGE = 2*FS_KB + FS_VB;      // 48KB
constexpr int FS_SMEM  = FS_QB + 2*FS_STAGE;   // 112KB

__device__ __forceinline__ uint32_t fs_swzk(int row, int c) {
    return (uint32_t)(row*128 + ((c ^ (row & 7)) << 4));
}
__device__ __forceinline__ uint32_t fs_swzv(int row, int c) {
    return (uint32_t)(row*256 + ((c ^ (row & 7)) << 4));
}

__device__ __forceinline__ void fs_loadQ(uint32_t qb, int tid, int bh, int q0,
                                         const mha_h* Qh) {
    #pragma unroll
    for (int i = tid; i < 1024; i += 256) {
        int row = i >> 3, c = i & 7;
        uint32_t off = fs_swzk(row, c);
        size_t g = ((size_t)bh*MHA_S + q0 + row)*MHA_DK + c*8;
        mha_cpa16(qb + off, Qh + g);
    }
}
__device__ __forceinline__ void fs_loadK_hi(uint32_t sb, int tid, int bh, int t,
                                            const mha_h* Kh) {
    #pragma unroll
    for (int i = tid; i < 1024; i += 256) {
        int row = i >> 3, c = i & 7;
        uint32_t off = fs_swzk(row, c);
        size_t g = ((size_t)bh*MHA_S + t*128 + row)*MHA_DK + c*8;
        mha_cpa16(sb + off, Kh + g);
    }
}
__device__ __forceinline__ void fs_loadKV(uint32_t sb, int tid, int bh, int t,
                                          const mha_h* Kh, const mha_h* Kl,
                                          const mha_h* Vh) {
    #pragma unroll
    for (int i = tid; i < 1024; i += 256) {
        int row = i >> 3, c = i & 7;
        uint32_t off = fs_swzk(row, c);
        size_t g = ((size_t)bh*MHA_S + t*128 + row)*MHA_DK + c*8;
        mha_cpa16(sb + off,         Kh + g);
        mha_cpa16(sb + FS_KB + off, Kl + g);
    }
    #pragma unroll
    for (int i = tid; i < 1024; i += 256) {
        int row = i >> 4, c = i & 15;
        uint32_t off = fs_swzv(row, c);
        size_t g = ((size_t)bh*MHA_DK + row)*MHA_S + t*128 + c*8;
        mha_cpa16(sb + 2*FS_KB + off, Vh + g);
    }
}

// 2-term 16x64 score half-tile: qh·(kh + kl), scaled by 1/8
__device__ __forceinline__ void fs_scores2(
    float acc[8][4], uint32_t kbase, int hf, int lane, const uint32_t qh[4][4])
{
    #pragma unroll
    for (int nt = 0; nt < 8; nt++)
        #pragma unroll
        for (int r = 0; r < 4; r++) acc[nt][r] = 0.f;
    #pragma unroll
    for (int j = 0; j < 4; j++) {
        uint32_t kh[8][2], kl[8][2];
        #pragma unroll
        for (int g = 0; g < 4; g++) {
            int r = hf*64 + g*16 + (lane & 15);
            int c = 2*j + (lane >> 4);
            uint32_t off = fs_swzk(r, c);
            uint32_t t0,t1,t2,t3;
            mha_ldsm4(t0,t1,t2,t3, kbase + off);
            kh[2*g][0]=t0; kh[2*g][1]=t2; kh[2*g+1][0]=t1; kh[2*g+1][1]=t3;
            mha_ldsm4(t0,t1,t2,t3, kbase + FS_KB + off);
            kl[2*g][0]=t0; kl[2*g][1]=t2; kl[2*g+1][0]=t1; kl[2*g+1][1]=t3;
        }
        #pragma unroll
        for (int nt = 0; nt < 8; nt++) {
            mha_mma(acc[nt], qh[j], kh[nt]);
            mha_mma(acc[nt], qh[j], kl[nt]);
        }
    }
    #pragma unroll
    for (int nt = 0; nt < 8; nt++)
        #pragma unroll
        for (int r = 0; r < 4; r++) acc[nt][r] *= 0.125f;
}

// 1-term (hi-only) scores for pass 1
__device__ __forceinline__ void fs_scores_hi(
    float acc[8][4], uint32_t kbase, int hf, int lane, const uint32_t qh[4][4])
{
    #pragma unroll
    for (int nt = 0; nt < 8; nt++)
        #pragma unroll
        for (int r = 0; r < 4; r++) acc[nt][r] = 0.f;
    #pragma unroll
    for (int j = 0; j < 4; j++) {
        uint32_t kh[8][2];
        #pragma unroll
        for (int g = 0; g < 4; g++) {
            int r = hf*64 + g*16 + (lane & 15);
            int c = 2*j + (lane >> 4);
            uint32_t off = fs_swzk(r, c);
            uint32_t t0,t1,t2,t3;
            mha_ldsm4(t0,t1,t2,t3, kbase + off);
            kh[2*g][0]=t0; kh[2*g][1]=t2; kh[2*g+1][0]=t1; kh[2*g+1][1]=t3;
        }
        #pragma unroll
        for (int nt = 0; nt < 8; nt++)
            mha_mma(acc[nt], qh[j], kh[nt]);
    }
    #pragma unroll
    for (int nt = 0; nt < 8; nt++)
        #pragma unroll
        for (int r = 0; r < 4; r++) acc[nt][r] *= 0.125f;
}

__global__ void __launch_bounds__(256) mha_flash(
    const mha_h* __restrict__ Qh,
    const mha_h* __restrict__ Kh, const mha_h* __restrict__ Kl,
    const mha_h* __restrict__ Vh,
    float* __restrict__ attn, mha_h* __restrict__ Oh)
{
    extern __shared__ char smem[];
    uint32_t sbase = (uint32_t)__cvta_generic_to_shared(smem);
    uint32_t qb  = sbase;
    uint32_t stg = sbase + FS_QB;

    int tid = threadIdx.x;
    int warp = tid >> 5, lane = tid & 31;
    int bh = blockIdx.y;
    int q0 = blockIdx.x * 128;

    uint32_t qfh[4][4];
    float s0 = 0.f, s1 = 0.f;

    // ---- pass 1: hi-only scores -> row sums of exp(S) ----
    fs_loadQ(qb, tid, bh, q0, Qh);
    fs_loadK_hi(stg, tid, bh, 0, Kh);
    mha_cp_commit();

    for (int t = 0; t < 16; t++) {
        if (t + 1 < 16) fs_loadK_hi(stg + ((t+1)&1)*FS_STAGE, tid, bh, t+1, Kh);
        mha_cp_commit();
        mha_cp_wait<1>(); __syncthreads();

        if (t == 0) {
            #pragma unroll
            for (int j = 0; j < 4; j++) {
                int r = warp*16 + (lane & 15);
                int c = 2*j + (lane >> 4);
                uint32_t off = fs_swzk(r, c);
                mha_ldsm4(qfh[j][0],qfh[j][1],qfh[j][2],qfh[j][3], qb + off);
            }
        }

        uint32_t kb = stg + (t&1)*FS_STAGE;
        #pragma unroll
        for (int hf = 0; hf < 2; hf++) {
            float acc[8][4];
            fs_scores_hi(acc, kb, hf, lane, qfh);
            #pragma unroll
            for (int nt = 0; nt < 8; nt++) {
                s0 += __expf(acc[nt][0]) + __expf(acc[nt][1]);
                s1 += __expf(acc[nt][2]) + __expf(acc[nt][3]);
            }
        }
        __syncthreads();
    }

    s0 += __shfl_xor_sync(0xffffffffu, s0, 1);
    s0 += __shfl_xor_sync(0xffffffffu, s0, 2);
    s1 += __shfl_xor_sync(0xffffffffu, s1, 1);
    s1 += __shfl_xor_sync(0xffffffffu, s1, 2);
    float inv0 = 1.f / s0, inv1 = 1.f / s1;

    float oacc[8][4];
    #pragma unroll
    for (int nd = 0; nd < 8; nd++)
        #pragma unroll
        for (int r = 0; r < 4; r++) oacc[nd][r] = 0.f;

    // ---- pass 2: 2-term scores, P = exp(S)*inv, write P, O += P·Vh ----
    fs_loadKV(stg, tid, bh, 0, Kh, Kl, Vh);
    mha_cp_commit();

    int qrow0 = q0 + warp*16 + (lane >> 2);
    for (int t = 0; t < 16; t++) {
        if (t + 1 < 16)
            fs_loadKV(stg + ((t+1)&1)*FS_STAGE, tid, bh, t+1, Kh, Kl, Vh);
        mha_cp_commit();
        mha_cp_wait<1>(); __syncthreads();

        uint32_t kb = stg + (t&1)*FS_STAGE;
        #pragma unroll
        for (int hf = 0; hf < 2; hf++) {
            float acc[8][4];
            fs_scores2(acc, kb, hf, lane, qfh);
            #pragma unroll
            for (int nt = 0; nt < 8; nt++) {
                acc[nt][0] = __expf(acc[nt][0])*inv0;
                acc[nt][1] = __expf(acc[nt][1])*inv0;
                acc[nt][2] = __expf(acc[nt][2])*inv1;
                acc[nt][3] = __expf(acc[nt][3])*inv1;
            }
            {
                size_t rb0 = ((size_t)bh*MHA_S + qrow0)    *MHA_S + t*128 + hf*64 + (lane&3)*2;
                size_t rb1 = ((size_t)bh*MHA_S + qrow0 + 8)*MHA_S + t*128 + hf*64 + (lane&3)*2;
                #pragma unroll
                for (int nt = 0; nt < 8; nt++) {
                    *(float2*)(attn + rb0 + nt*8) = make_float2(acc[nt][0], acc[nt][1]);
                    *(float2*)(attn + rb1 + nt*8) = make_float2(acc[nt][2], acc[nt][3]);
                }
            }
            #pragma unroll
            for (int kk = 0; kk < 4; kk++) {
                uint32_t pah[4];
                pah[0] = mha_pack(acc[2*kk][0],   acc[2*kk][1]);
                pah[1] = mha_pack(acc[2*kk][2],   acc[2*kk][3]);
                pah[2] = mha_pack(acc[2*kk+1][0], acc[2*kk+1][1]);
                pah[3] = mha_pack(acc[2*kk+1][2], acc[2*kk+1][3]);

                uint32_t vbh[8][2];
                #pragma unroll
                for (int g = 0; g < 4; g++) {
                    int r = g*16 + (lane & 15);
                    int c = 2*(hf*4 + kk) + (lane >> 4);
                    uint32_t off = fs_swzv(r, c);
                    uint32_t t0,t1,t2,t3;
                    mha_ldsm4(t0,t1,t2,t3, kb + 2*FS_KB + off);
                    vbh[2*g][0]=t0; vbh[2*g][1]=t2; vbh[2*g+1][0]=t1; vbh[2*g+1][1]=t3;
                }
                #pragma unroll
                for (int nd = 0; nd < 8; nd++)
                    mha_mma(oacc[nd], pah, vbh[nd]);
            }
        }
        __syncthreads();
    }

    // ---- O epilogue: hi-only fp16 [b][s][d] ----
    int b = bh >> 4, h = bh & 15;
    #pragma unroll
    for (int nd = 0; nd < 8; nd++) {
        int dk = nd*8 + (lane & 3)*2;
        size_t i0 = ((size_t)(b*MHA_S + qrow0))    *MHA_D + h*MHA_DK + dk;
        size_t i1 = ((size_t)(b*MHA_S + qrow0 + 8))*MHA_D + h*MHA_DK + dk;
        *(mha_h2*)(Oh + i0) = __floats2half2_rn(oacc[nd][0], oacc[nd][1]);
        *(mha_h2*)(Oh + i1) = __floats2half2_rn(oacc[nd][2], oacc[nd][3]);
    }
}

// ---------------- host ----------------
extern "C" void kernel_launch(void* const* d_in, const int* in_sizes, int n_in,
                              void* d_out, int out_size)
{
    (void)in_sizes; (void)n_in; (void)out_size;
    const float* q  = (const float*)d_in[0];
    const float* k  = (const float*)d_in[1];
    const float* v  = (const float*)d_in[2];
    const float* wq = (const float*)d_in[3];
    const float* bq = (const float*)d_in[4];
    const float* wk = (const float*)d_in[5];
    const float* bk = (const float*)d_in[6];
    const float* wv = (const float*)d_in[7];
    const float* bv = (const float*)d_in[8];
    const float* wo = (const float*)d_in[9];
    const float* bo = (const float*)d_in[10];

    float* out  = (float*)d_out;
    float* attn = out + (size_t)MHA_B * MHA_S * MHA_D;

    mha_h *inh, *wh, *wl, *Qh, *Kh, *Kl, *Vth, *Oh;
    cudaGetSymbolAddress((void**)&inh, g_inh);
    cudaGetSymbolAddress((void**)&wh,  g_wh);
    cudaGetSymbolAddress((void**)&wl,  g_wl);
    cudaGetSymbolAddress((void**)&Qh,  g_Qh);
    cudaGetSymbolAddress((void**)&Kh,  g_Kh);
    cudaGetSymbolAddress((void**)&Kl,  g_Kl);
    cudaGetSymbolAddress((void**)&Vth, g_Vth);
    cudaGetSymbolAddress((void**)&Oh,  g_Oh);

    const size_t NIN = (size_t)8192*1024;
    const size_t NW  = (size_t)1024*1024;

    mha_split_in3<<<dim3((unsigned)(NIN/4/256), 3), 256>>>(q, k, v, inh);
    mha_split_w4 <<<dim3((unsigned)(NW/4/256),  4), 256>>>(wq, wk, wv, wo, wh, wl);

    auto gq  = mha_gemm<128,128,2,4,EP_Q_HEAD>;
    auto gk  = mha_gemm<128,128,2,4,EP_K_HEAD>;
    auto gv2 = mha_gemm<128,128,2,4,EP_V_HEADT>;
    auto gou = mha_gemm<128,128,2,4,EP_OUT>;

    const int SM128 = 2 * (128*64 + 2*128*64);   // 49152 B
    cudaFuncSetAttribute(gq,  cudaFuncAttributeMaxDynamicSharedMemorySize, SM128);
    cudaFuncSetAttribute(gk,  cudaFuncAttributeMaxDynamicSharedMemorySize, SM128);
    cudaFuncSetAttribute(gv2, cudaFuncAttributeMaxDynamicSharedMemorySize, SM128);
    cudaFuncSetAttribute(gou, cudaFuncAttributeMaxDynamicSharedMemorySize, SM128);
    cudaFuncSetAttribute(mha_flash, cudaFuncAttributeMaxDynamicSharedMemorySize, FS_SMEM);

    dim3 t(256);

    dim3 gproj(1024/128, 8192/128, 1);
    gq <<<gproj, t, SM128>>>(inh,         wh,        wl,        bq,
                             nullptr, Qh, nullptr, 8192, 1024, 1024);
    gk <<<gproj, t, SM128>>>(inh + NIN,   wh + NW,   wl + NW,   bk,
                             nullptr, Kh, Kl, 8192, 1024, 1024);
    gv2<<<gproj, t, SM128>>>(inh + 2*NIN, wh + 2*NW, wl + 2*NW, bv,
                             nullptr, Vth, nullptr, 8192, 1024, 1024);

    dim3 gf(16, MHA_B*MHA_H);
    mha_flash<<<gf, t, FS_SMEM>>>(Qh, Kh, Kl, Vth, attn, Oh);

    gou<<<gproj, t, SM128>>>(Oh, wh + 3*NW, wl + 3*NW, bo,
                             out, nullptr, nullptr, 8192, 1024, 1024);
}

// round 12
// speedup vs baseline: 1.4305x; 1.1366x over previous
#include <cuda_runtime.h>
#include <cuda_fp16.h>
#include <cstdint>
#include <cstddef>

typedef __half  mha_h;
typedef __half2 mha_h2;

constexpr int MHA_B  = 4;
constexpr int MHA_S  = 2048;
constexpr int MHA_D  = 1024;
constexpr int MHA_H  = 16;
constexpr int MHA_DK = 64;

// ---------------- scratch ----------------
__device__ mha_h g_inh[(size_t)3*8192*1024];                     // input hi only
__device__ mha_h g_wh [(size_t)4*1024*1024];                     // weight hi
__device__ mha_h g_wl [(size_t)4*1024*1024];                     // weight lo (K, only)
__device__ mha_h g_Qh[(size_t)8388608];                          // [bh][s][dk] hi
__device__ mha_h g_Kh[(size_t)8388608], g_Kl[(size_t)8388608];   // [bh][s][dk]
__device__ mha_h g_Vth[(size_t)8388608];                         // [bh][dk][s] hi
__device__ mha_h g_Oh[(size_t)8388608];                          // [b][s][d] hi

// ---------------- PTX helpers ----------------
__device__ __forceinline__ void mha_cpa16(uint32_t dst, const void* src) {
    asm volatile("cp.async.cg.shared.global [%0], [%1], 16;\n" :: "r"(dst), "l"(src));
}
__device__ __forceinline__ void mha_cp_commit() { asm volatile("cp.async.commit_group;\n"); }
template<int N> __device__ __forceinline__ void mha_cp_wait() {
    asm volatile("cp.async.wait_group %0;\n" :: "n"(N));
}
__device__ __forceinline__ void mha_ldsm4(uint32_t &r0, uint32_t &r1, uint32_t &r2,
                                          uint32_t &r3, uint32_t addr) {
    asm volatile("ldmatrix.sync.aligned.m8n8.x4.shared.b16 {%0,%1,%2,%3}, [%4];\n"
        : "=r"(r0),"=r"(r1),"=r"(r2),"=r"(r3) : "r"(addr));
}
__device__ __forceinline__ void mha_mma(float* d, const uint32_t* a, const uint32_t* b) {
    asm volatile("mma.sync.aligned.m16n8k16.row.col.f32.f16.f16.f32 "
      "{%0,%1,%2,%3}, {%4,%5,%6,%7}, {%8,%9}, {%0,%1,%2,%3};\n"
      : "+f"(d[0]),"+f"(d[1]),"+f"(d[2]),"+f"(d[3])
      : "r"(a[0]),"r"(a[1]),"r"(a[2]),"r"(a[3]),"r"(b[0]),"r"(b[1]));
}
__device__ __forceinline__ void mha_split2(float v0, float v1, mha_h2 &h2, mha_h2 &l2) {
    mha_h h0 = __float2half_rn(v0);
    mha_h h1 = __float2half_rn(v1);
    mha_h l0 = __float2half_rn(v0 - __half2float(h0));
    mha_h l1 = __float2half_rn(v1 - __half2float(h1));
    h2 = __halves2half2(h0, h1);
    l2 = __halves2half2(l0, l1);
}
__device__ __forceinline__ uint32_t mha_pack(float a, float b) {
    mha_h2 t = __floats2half2_rn(a, b);
    return *(uint32_t*)&t;
}

// ---------------- input/weight split ----------------
__global__ void mha_split_in3(const float* __restrict__ q, const float* __restrict__ k,
                              const float* __restrict__ v, mha_h* __restrict__ h) {
    const size_t NIN = (size_t)8192*1024;
    int seg = blockIdx.y;
    const float* x = (seg == 0) ? q : (seg == 1) ? k : v;
    size_t i = (size_t)blockIdx.x*blockDim.x + threadIdx.x;
    if (i >= NIN/4) return;
    float4 val = ((const float4*)x)[i];
    size_t o = (size_t)seg*(NIN/2) + 2*i;
    ((mha_h2*)h)[o]   = __floats2half2_rn(val.x, val.y);
    ((mha_h2*)h)[o+1] = __floats2half2_rn(val.z, val.w);
}
__global__ void mha_split_w4(const float* __restrict__ wq, const float* __restrict__ wk,
                             const float* __restrict__ wv, const float* __restrict__ wo,
                             mha_h* __restrict__ h, mha_h* __restrict__ l) {
    const size_t NW = (size_t)1024*1024;
    int seg = blockIdx.y;
    const float* x = (seg == 0) ? wq : (seg == 1) ? wk : (seg == 2) ? wv : wo;
    size_t i = (size_t)blockIdx.x*blockDim.x + threadIdx.x;
    if (i >= NW/4) return;
    float4 val = ((const float4*)x)[i];
    mha_h2 h0, l0, h1, l1;
    mha_split2(val.x, val.y, h0, l0);
    mha_split2(val.z, val.w, h1, l1);
    size_t o = (size_t)seg*(NW/2) + 2*i;
    ((mha_h2*)h)[o]   = h0;  ((mha_h2*)h)[o+1] = h1;
    ((mha_h2*)l)[o]   = l0;  ((mha_h2*)l)[o+1] = l1;
}

// ---------------- projection GEMM: C = Xh(M,K) @ W(N,K)^T (1 or 2 terms) ----
constexpr int EP_Q_HEAD  = 0;   // head-major, hi only
constexpr int EP_K_HEAD  = 1;   // head-major, hi+lo
constexpr int EP_V_HEADT = 2;   // transposed head-major, hi only
constexpr int EP_OUT     = 4;   // fp32 + bias

__device__ __forceinline__ uint32_t mha_swz(int row, int kc) {
    return (uint32_t)(row*64 + ((kc ^ ((row >> 1) & 3)) << 4));
}

template<int BM, int BN, int NTERMS>
__device__ __forceinline__ void mha_issue(
    uint32_t s0, int tid, int bm, int bn, int kk, int K,
    const mha_h* pAh, const mha_h* pBh, const mha_h* pBl)
{
    constexpr int ABYTES = BM * 64;
    constexpr int BBYTES = BN * 64;
    #pragma unroll
    for (int c = tid; c < BM*4; c += 256) {
        int row = c >> 2, kc = c & 3;
        uint32_t off = mha_swz(row, kc);
        size_t g = (size_t)(bm + row) * K + kk + kc*8;
        mha_cpa16(s0 + off, pAh + g);
    }
    #pragma unroll
    for (int c = tid; c < BN*4; c += 256) {
        int row = c >> 2, kc = c & 3;
        uint32_t off = mha_swz(row, kc);
        size_t g = (size_t)(bn + row) * K + kk + kc*8;
        mha_cpa16(s0 + ABYTES + off, pBh + g);
        if (NTERMS == 2)
            mha_cpa16(s0 + ABYTES + BBYTES + off, pBl + g);
    }
}

template<int BM, int BN, int WSM, int WSN, int MODE, int NTERMS>
__global__ void __launch_bounds__(256, 2) mha_gemm(
    const mha_h* __restrict__ Ah,
    const mha_h* __restrict__ Bh, const mha_h* __restrict__ Bl,
    const float* __restrict__ bias,
    float* __restrict__ Cf, mha_h* __restrict__ Ch, mha_h* __restrict__ Cl,
    int M, int N, int K)
{
    constexpr int WM = BM / WSM, WN = BN / WSN;
    constexpr int MT = WM / 16,  NT = WN / 8;
    constexpr int ABYTES = BM * 64;
    constexpr int BBYTES = BN * 64;
    constexpr int STAGE  = ABYTES + NTERMS*BBYTES;

    extern __shared__ char smem[];
    uint32_t sbase = (uint32_t)__cvta_generic_to_shared(smem);

    int tid  = threadIdx.x;
    int warp = tid >> 5, lane = tid & 31;
    int wm = warp / WSN, wn = warp % WSN;
    int bm = blockIdx.y * BM, bn = blockIdx.x * BN;

    float acc[MT][NT][4];
    #pragma unroll
    for (int i = 0; i < MT; i++)
        #pragma unroll
        for (int j = 0; j < NT; j++)
            #pragma unroll
            for (int r = 0; r < 4; r++) acc[i][j][r] = 0.f;

    int ITERS = K / 32;
    mha_issue<BM,BN,NTERMS>(sbase, tid, bm, bn, 0, K, Ah, Bh, Bl);
    mha_cp_commit();

    for (int it = 0; it < ITERS; it++) {
        if (it + 1 < ITERS)
            mha_issue<BM,BN,NTERMS>(sbase + ((it+1)&1)*STAGE, tid, bm, bn, (it+1)*32, K,
                                    Ah, Bh, Bl);
        mha_cp_commit();
        mha_cp_wait<1>(); __syncthreads();

        uint32_t sAh0 = sbase + (it&1)*STAGE;
        uint32_t sBh0 = sAh0 + ABYTES;
        uint32_t sBl0 = sBh0 + BBYTES;

        #pragma unroll
        for (int ks = 0; ks < 2; ks++) {
            int kc0 = ks * 2;
            uint32_t fah[MT][4], fbh[NT][2], fbl[NT][2];
            #pragma unroll
            for (int mt = 0; mt < MT; mt++) {
                int r  = wm*WM + mt*16 + (lane & 15);
                int kc = kc0 + (lane >> 4);
                uint32_t off = mha_swz(r, kc);
                mha_ldsm4(fah[mt][0],fah[mt][1],fah[mt][2],fah[mt][3], sAh0 + off);
            }
            #pragma unroll
            for (int g = 0; g < NT/2; g++) {
                int r  = wn*WN + g*16 + (lane & 15);
                int kc = kc0 + (lane >> 4);
                uint32_t off = mha_swz(r, kc);
                uint32_t t0,t1,t2,t3;
                mha_ldsm4(t0,t1,t2,t3, sBh0 + off);
                fbh[2*g][0]=t0; fbh[2*g][1]=t2; fbh[2*g+1][0]=t1; fbh[2*g+1][1]=t3;
                if (NTERMS == 2) {
                    mha_ldsm4(t0,t1,t2,t3, sBl0 + off);
                    fbl[2*g][0]=t0; fbl[2*g][1]=t2; fbl[2*g+1][0]=t1; fbl[2*g+1][1]=t3;
                }
            }
            #pragma unroll
            for (int mt = 0; mt < MT; mt++)
                #pragma unroll
                for (int nt = 0; nt < NT; nt++) {
                    mha_mma(acc[mt][nt], fah[mt], fbh[nt]);
                    if (NTERMS == 2)
                        mha_mma(acc[mt][nt], fah[mt], fbl[nt]);
                }
        }
        __syncthreads();
    }

    #pragma unroll
    for (int mt = 0; mt < MT; mt++)
        #pragma unroll
        for (int nt = 0; nt < NT; nt++) {
            int r0 = bm + wm*WM + mt*16 + (lane >> 2);
            int c0 = bn + wn*WN + nt*8  + (lane & 3)*2;
            #pragma unroll
            for (int half = 0; half < 2; half++) {
                int r = r0 + half*8;
                float v0 = acc[mt][nt][2*half], v1 = acc[mt][nt][2*half+1];
                if (MODE == EP_OUT) {
                    float2 o = make_float2(v0 + bias[c0], v1 + bias[c0+1]);
                    *(float2*)(Cf + (size_t)r*N + c0) = o;
                } else if (MODE == EP_Q_HEAD) {
                    v0 += bias[c0]; v1 += bias[c0+1];
                    int b = r >> 11, s = r & (MHA_S-1);
                    int h = c0 >> 6, dk = c0 & 63;
                    size_t idx = (((size_t)(b*MHA_H + h))*MHA_S + s)*MHA_DK + dk;
                    *(mha_h2*)(Ch + idx) = __floats2half2_rn(v0, v1);
                } else if (MODE == EP_K_HEAD) {
                    v0 += bias[c0]; v1 += bias[c0+1];
                    int b = r >> 11, s = r & (MHA_S-1);
                    int h = c0 >> 6, dk = c0 & 63;
                    size_t idx = (((size_t)(b*MHA_H + h))*MHA_S + s)*MHA_DK + dk;
                    mha_h2 h2, l2; mha_split2(v0, v1, h2, l2);
                    *(mha_h2*)(Ch + idx) = h2;
                    *(mha_h2*)(Cl + idx) = l2;
                } else { // EP_V_HEADT (hi only)
                    v0 += bias[c0]; v1 += bias[c0+1];
                    int b = r >> 11, s = r & (MHA_S-1);
                    int h = c0 >> 6, dk = c0 & 63;
                    size_t idx = (((size_t)(b*MHA_H + h))*MHA_DK + dk)*MHA_S + s;
                    Ch[idx]         = __float2half_rn(v0);
                    Ch[idx + MHA_S] = __float2half_rn(v1);
                }
            }
        }
}

// =================== fused flash attention (unchanged from R10) ===============
constexpr int FS_QB    = 128*128;              // Q hi 16KB
constexpr int FS_KB    = 128*128;              // K half 16KB
constexpr int FS_VB    = 64*256;               // V hi 16KB
constexpr int FS_STAGE = 2*FS_KB + FS_VB;      // 48KB
constexpr int FS_SMEM  = FS_QB + 2*FS_STAGE;   // 112KB

__device__ __forceinline__ uint32_t fs_swzk(int row, int c) {
    return (uint32_t)(row*128 + ((c ^ (row & 7)) << 4));
}
__device__ __forceinline__ uint32_t fs_swzv(int row, int c) {
    return (uint32_t)(row*256 + ((c ^ (row & 7)) << 4));
}

__device__ __forceinline__ void fs_loadQ(uint32_t qb, int tid, int bh, int q0,
                                         const mha_h* Qh) {
    #pragma unroll
    for (int i = tid; i < 1024; i += 256) {
        int row = i >> 3, c = i & 7;
        uint32_t off = fs_swzk(row, c);
        size_t g = ((size_t)bh*MHA_S + q0 + row)*MHA_DK + c*8;
        mha_cpa16(qb + off, Qh + g);
    }
}
__device__ __forceinline__ void fs_loadK_hi(uint32_t sb, int tid, int bh, int t,
                                            const mha_h* Kh) {
    #pragma unroll
    for (int i = tid; i < 1024; i += 256) {
        int row = i >> 3, c = i & 7;
        uint32_t off = fs_swzk(row, c);
        size_t g = ((size_t)bh*MHA_S + t*128 + row)*MHA_DK + c*8;
        mha_cpa16(sb + off, Kh + g);
    }
}
__device__ __forceinline__ void fs_loadKV(uint32_t sb, int tid, int bh, int t,
                                          const mha_h* Kh, const mha_h* Kl,
                                          const mha_h* Vh) {
    #pragma unroll
    for (int i = tid; i < 1024; i += 256) {
        int row = i >> 3, c = i & 7;
        uint32_t off = fs_swzk(row, c);
        size_t g = ((size_t)bh*MHA_S + t*128 + row)*MHA_DK + c*8;
        mha_cpa16(sb + off,         Kh + g);
        mha_cpa16(sb + FS_KB + off, Kl + g);
    }
    #pragma unroll
    for (int i = tid; i < 1024; i += 256) {
        int row = i >> 4, c = i & 15;
        uint32_t off = fs_swzv(row, c);
        size_t g = ((size_t)bh*MHA_DK + row)*MHA_S + t*128 + c*8;
        mha_cpa16(sb + 2*FS_KB + off, Vh + g);
    }
}

__device__ __forceinline__ void fs_scores2(
    float acc[8][4], uint32_t kbase, int hf, int lane, const uint32_t qh[4][4])
{
    #pragma unroll
    for (int nt = 0; nt < 8; nt++)
        #pragma unroll
        for (int r = 0; r < 4; r++) acc[nt][r] = 0.f;
    #pragma unroll
    for (int j = 0; j < 4; j++) {
        uint32_t kh[8][2], kl[8][2];
        #pragma unroll
        for (int g = 0; g < 4; g++) {
            int r = hf*64 + g*16 + (lane & 15);
            int c = 2*j + (lane >> 4);
            uint32_t off = fs_swzk(r, c);
            uint32_t t0,t1,t2,t3;
            mha_ldsm4(t0,t1,t2,t3, kbase + off);
            kh[2*g][0]=t0; kh[2*g][1]=t2; kh[2*g+1][0]=t1; kh[2*g+1][1]=t3;
            mha_ldsm4(t0,t1,t2,t3, kbase + FS_KB + off);
            kl[2*g][0]=t0; kl[2*g][1]=t2; kl[2*g+1][0]=t1; kl[2*g+1][1]=t3;
        }
        #pragma unroll
        for (int nt = 0; nt < 8; nt++) {
            mha_mma(acc[nt], qh[j], kh[nt]);
            mha_mma(acc[nt], qh[j], kl[nt]);
        }
    }
    #pragma unroll
    for (int nt = 0; nt < 8; nt++)
        #pragma unroll
        for (int r = 0; r < 4; r++) acc[nt][r] *= 0.125f;
}

__device__ __forceinline__ void fs_scores_hi(
    float acc[8][4], uint32_t kbase, int hf, int lane, const uint32_t qh[4][4])
{
    #pragma unroll
    for (int nt = 0; nt < 8; nt++)
        #pragma unroll
        for (int r = 0; r < 4; r++) acc[nt][r] = 0.f;
    #pragma unroll
    for (int j = 0; j < 4; j++) {
        uint32_t kh[8][2];
        #pragma unroll
        for (int g = 0; g < 4; g++) {
            int r = hf*64 + g*16 + (lane & 15);
            int c = 2*j + (lane >> 4);
            uint32_t off = fs_swzk(r, c);
            uint32_t t0,t1,t2,t3;
            mha_ldsm4(t0,t1,t2,t3, kbase + off);
            kh[2*g][0]=t0; kh[2*g][1]=t2; kh[2*g+1][0]=t1; kh[2*g+1][1]=t3;
        }
        #pragma unroll
        for (int nt = 0; nt < 8; nt++)
            mha_mma(acc[nt], qh[j], kh[nt]);
    }
    #pragma unroll
    for (int nt = 0; nt < 8; nt++)
        #pragma unroll
        for (int r = 0; r < 4; r++) acc[nt][r] *= 0.125f;
}

__global__ void __launch_bounds__(256) mha_flash(
    const mha_h* __restrict__ Qh,
    const mha_h* __restrict__ Kh, const mha_h* __restrict__ Kl,
    const mha_h* __restrict__ Vh,
    float* __restrict__ attn, mha_h* __restrict__ Oh)
{
    extern __shared__ char smem[];
    uint32_t sbase = (uint32_t)__cvta_generic_to_shared(smem);
    uint32_t qb  = sbase;
    uint32_t stg = sbase + FS_QB;

    int tid = threadIdx.x;
    int warp = tid >> 5, lane = tid & 31;
    int bh = blockIdx.y;
    int q0 = blockIdx.x * 128;

    uint32_t qfh[4][4];
    float s0 = 0.f, s1 = 0.f;

    fs_loadQ(qb, tid, bh, q0, Qh);
    fs_loadK_hi(stg, tid, bh, 0, Kh);
    mha_cp_commit();

    for (int t = 0; t < 16; t++) {
        if (t + 1 < 16) fs_loadK_hi(stg + ((t+1)&1)*FS_STAGE, tid, bh, t+1, Kh);
        mha_cp_commit();
        mha_cp_wait<1>(); __syncthreads();

        if (t == 0) {
            #pragma unroll
            for (int j = 0; j < 4; j++) {
                int r = warp*16 + (lane & 15);
                int c = 2*j + (lane >> 4);
                uint32_t off = fs_swzk(r, c);
                mha_ldsm4(qfh[j][0],qfh[j][1],qfh[j][2],qfh[j][3], qb + off);
            }
        }

        uint32_t kb = stg + (t&1)*FS_STAGE;
        #pragma unroll
        for (int hf = 0; hf < 2; hf++) {
            float acc[8][4];
            fs_scores_hi(acc, kb, hf, lane, qfh);
            #pragma unroll
            for (int nt = 0; nt < 8; nt++) {
                s0 += __expf(acc[nt][0]) + __expf(acc[nt][1]);
                s1 += __expf(acc[nt][2]) + __expf(acc[nt][3]);
            }
        }
        __syncthreads();
    }

    s0 += __shfl_xor_sync(0xffffffffu, s0, 1);
    s0 += __shfl_xor_sync(0xffffffffu, s0, 2);
    s1 += __shfl_xor_sync(0xffffffffu, s1, 1);
    s1 += __shfl_xor_sync(0xffffffffu, s1, 2);
    float inv0 = 1.f / s0, inv1 = 1.f / s1;

    float oacc[8][4];
    #pragma unroll
    for (int nd = 0; nd < 8; nd++)
        #pragma unroll
        for (int r = 0; r < 4; r++) oacc[nd][r] = 0.f;

    fs_loadKV(stg, tid, bh, 0, Kh, Kl, Vh);
    mha_cp_commit();

    int qrow0 = q0 + warp*16 + (lane >> 2);
    for (int t = 0; t < 16; t++) {
        if (t + 1 < 16)
            fs_loadKV(stg + ((t+1)&1)*FS_STAGE, tid, bh, t+1, Kh, Kl, Vh);
        mha_cp_commit();
        mha_cp_wait<1>(); __syncthreads();

        uint32_t kb = stg + (t&1)*FS_STAGE;
        #pragma unroll
        for (int hf = 0; hf < 2; hf++) {
            float acc[8][4];
            fs_scores2(acc, kb, hf, lane, qfh);
            #pragma unroll
            for (int nt = 0; nt < 8; nt++) {
                acc[nt][0] = __expf(acc[nt][0])*inv0;
                acc[nt][1] = __expf(acc[nt][1])*inv0;
                acc[nt][2] = __expf(acc[nt][2])*inv1;
                acc[nt][3] = __expf(acc[nt][3])*inv1;
            }
            {
                size_t rb0 = ((size_t)bh*MHA_S + qrow0)    *MHA_S + t*128 + hf*64 + (lane&3)*2;
                size_t rb1 = ((size_t)bh*MHA_S + qrow0 + 8)*MHA_S + t*128 + hf*64 + (lane&3)*2;
                #pragma unroll
                for (int nt = 0; nt < 8; nt++) {
                    *(float2*)(attn + rb0 + nt*8) = make_float2(acc[nt][0], acc[nt][1]);
                    *(float2*)(attn + rb1 + nt*8) = make_float2(acc[nt][2], acc[nt][3]);
                }
            }
            #pragma unroll
            for (int kk = 0; kk < 4; kk++) {
                uint32_t pah[4];
                pah[0] = mha_pack(acc[2*kk][0],   acc[2*kk][1]);
                pah[1] = mha_pack(acc[2*kk][2],   acc[2*kk][3]);
                pah[2] = mha_pack(acc[2*kk+1][0], acc[2*kk+1][1]);
                pah[3] = mha_pack(acc[2*kk+1][2], acc[2*kk+1][3]);

                uint32_t vbh[8][2];
                #pragma unroll
                for (int g = 0; g < 4; g++) {
                    int r = g*16 + (lane & 15);
                    int c = 2*(hf*4 + kk) + (lane >> 4);
                    uint32_t off = fs_swzv(r, c);
                    uint32_t t0,t1,t2,t3;
                    mha_ldsm4(t0,t1,t2,t3, kb + 2*FS_KB + off);
                    vbh[2*g][0]=t0; vbh[2*g][1]=t2; vbh[2*g+1][0]=t1; vbh[2*g+1][1]=t3;
                }
                #pragma unroll
                for (int nd = 0; nd < 8; nd++)
                    mha_mma(oacc[nd], pah, vbh[nd]);
            }
        }
        __syncthreads();
    }

    int b = bh >> 4, h = bh & 15;
    #pragma unroll
    for (int nd = 0; nd < 8; nd++) {
        int dk = nd*8 + (lane & 3)*2;
        size_t i0 = ((size_t)(b*MHA_S + qrow0))    *MHA_D + h*MHA_DK + dk;
        size_t i1 = ((size_t)(b*MHA_S + qrow0 + 8))*MHA_D + h*MHA_DK + dk;
        *(mha_h2*)(Oh + i0) = __floats2half2_rn(oacc[nd][0], oacc[nd][1]);
        *(mha_h2*)(Oh + i1) = __floats2half2_rn(oacc[nd][2], oacc[nd][3]);
    }
}

// ---------------- host ----------------
extern "C" void kernel_launch(void* const* d_in, const int* in_sizes, int n_in,
                              void* d_out, int out_size)
{
    (void)in_sizes; (void)n_in; (void)out_size;
    const float* q  = (const float*)d_in[0];
    const float* k  = (const float*)d_in[1];
    const float* v  = (const float*)d_in[2];
    const float* wq = (const float*)d_in[3];
    const float* bq = (const float*)d_in[4];
    const float* wk = (const float*)d_in[5];
    const float* bk = (const float*)d_in[6];
    const float* wv = (const float*)d_in[7];
    const float* bv = (const float*)d_in[8];
    const float* wo = (const float*)d_in[9];
    const float* bo = (const float*)d_in[10];

    float* out  = (float*)d_out;
    float* attn = out + (size_t)MHA_B * MHA_S * MHA_D;

    mha_h *inh, *wh, *wl, *Qh, *Kh, *Kl, *Vth, *Oh;
    cudaGetSymbolAddress((void**)&inh, g_inh);
    cudaGetSymbolAddress((void**)&wh,  g_wh);
    cudaGetSymbolAddress((void**)&wl,  g_wl);
    cudaGetSymbolAddress((void**)&Qh,  g_Qh);
    cudaGetSymbolAddress((void**)&Kh,  g_Kh);
    cudaGetSymbolAddress((void**)&Kl,  g_Kl);
    cudaGetSymbolAddress((void**)&Vth, g_Vth);
    cudaGetSymbolAddress((void**)&Oh,  g_Oh);

    const size_t NIN = (size_t)8192*1024;
    const size_t NW  = (size_t)1024*1024;

    mha_split_in3<<<dim3((unsigned)(NIN/4/256), 3), 256>>>(q, k, v, inh);
    mha_split_w4 <<<dim3((unsigned)(NW/4/256),  4), 256>>>(wq, wk, wv, wo, wh, wl);

    auto gq  = mha_gemm<128,128,2,4,EP_Q_HEAD, 1>;   // Q: 1-term
    auto gk  = mha_gemm<128,128,2,4,EP_K_HEAD, 2>;   // K: 2-term
    auto gv2 = mha_gemm<128,128,2,4,EP_V_HEADT,1>;   // V: 1-term
    auto gou = mha_gemm<128,128,2,4,EP_OUT,    1>;   // out: 1-term

    const int SM1 = 2 * (128*64 + 128*64);     // 32768 B
    const int SM2 = 2 * (128*64 + 2*128*64);   // 49152 B
    cudaFuncSetAttribute(gq,  cudaFuncAttributeMaxDynamicSharedMemorySize, SM1);
    cudaFuncSetAttribute(gk,  cudaFuncAttributeMaxDynamicSharedMemorySize, SM2);
    cudaFuncSetAttribute(gv2, cudaFuncAttributeMaxDynamicSharedMemorySize, SM1);
    cudaFuncSetAttribute(gou, cudaFuncAttributeMaxDynamicSharedMemorySize, SM1);
    cudaFuncSetAttribute(mha_flash, cudaFuncAttributeMaxDynamicSharedMemorySize, FS_SMEM);

    dim3 t(256);

    dim3 gproj(1024/128, 8192/128, 1);
    gq <<<gproj, t, SM1>>>(inh,         wh,        nullptr,   bq,
                           nullptr, Qh, nullptr, 8192, 1024, 1024);
    gk <<<gproj, t, SM2>>>(inh + NIN,   wh + NW,   wl + NW,   bk,
                           nullptr, Kh, Kl, 8192, 1024, 1024);
    gv2<<<gproj, t, SM1>>>(inh + 2*NIN, wh + 2*NW, nullptr,   bv,
                           nullptr, Vth, nullptr, 8192, 1024, 1024);

    dim3 gf(16, MHA_B*MHA_H);
    mha_flash<<<gf, t, FS_SMEM>>>(Qh, Kh, Kl, Vth, attn, Oh);

    gou<<<gproj, t, SM1>>>(Oh, wh + 3*NW, nullptr, bo,
                           out, nullptr, nullptr, 8192, 1024, 1024);
}

// round 13
// speedup vs baseline: 1.6980x; 1.1870x over previous
#include <cuda_runtime.h>
#include <cuda_fp16.h>
#include <cstdint>
#include <cstddef>

typedef __half  mha_h;
typedef __half2 mha_h2;

constexpr int MHA_B  = 4;
constexpr int MHA_S  = 2048;
constexpr int MHA_D  = 1024;
constexpr int MHA_H  = 16;
constexpr int MHA_DK = 64;

// ---------------- scratch ----------------
__device__ mha_h g_inh[(size_t)3*8192*1024];                     // input hi
__device__ mha_h g_wh [(size_t)4*1024*1024];                     // weight hi
__device__ mha_h g_Qh[(size_t)8388608];                          // [bh][s][dk] hi
__device__ mha_h g_Kh[(size_t)8388608];                          // [bh][s][dk] hi
__device__ mha_h g_Vth[(size_t)8388608];                         // [bh][dk][s] hi
__device__ mha_h g_Oh[(size_t)8388608];                          // [b][s][d] hi

// ---------------- PTX helpers ----------------
__device__ __forceinline__ void mha_cpa16(uint32_t dst, const void* src) {
    asm volatile("cp.async.cg.shared.global [%0], [%1], 16;\n" :: "r"(dst), "l"(src));
}
__device__ __forceinline__ void mha_cp_commit() { asm volatile("cp.async.commit_group;\n"); }
template<int N> __device__ __forceinline__ void mha_cp_wait() {
    asm volatile("cp.async.wait_group %0;\n" :: "n"(N));
}
__device__ __forceinline__ void mha_ldsm4(uint32_t &r0, uint32_t &r1, uint32_t &r2,
                                          uint32_t &r3, uint32_t addr) {
    asm volatile("ldmatrix.sync.aligned.m8n8.x4.shared.b16 {%0,%1,%2,%3}, [%4];\n"
        : "=r"(r0),"=r"(r1),"=r"(r2),"=r"(r3) : "r"(addr));
}
__device__ __forceinline__ void mha_mma(float* d, const uint32_t* a, const uint32_t* b) {
    asm volatile("mma.sync.aligned.m16n8k16.row.col.f32.f16.f16.f32 "
      "{%0,%1,%2,%3}, {%4,%5,%6,%7}, {%8,%9}, {%0,%1,%2,%3};\n"
      : "+f"(d[0]),"+f"(d[1]),"+f"(d[2]),"+f"(d[3])
      : "r"(a[0]),"r"(a[1]),"r"(a[2]),"r"(a[3]),"r"(b[0]),"r"(b[1]));
}
__device__ __forceinline__ uint32_t mha_pack(float a, float b) {
    mha_h2 t = __floats2half2_rn(a, b);
    return *(uint32_t*)&t;
}

// ---------------- input/weight split (hi only) ----------------
__global__ void mha_split_in3(const float* __restrict__ q, const float* __restrict__ k,
                              const float* __restrict__ v, mha_h* __restrict__ h) {
    const size_t NIN = (size_t)8192*1024;
    int seg = blockIdx.y;
    const float* x = (seg == 0) ? q : (seg == 1) ? k : v;
    size_t i = (size_t)blockIdx.x*blockDim.x + threadIdx.x;
    if (i >= NIN/4) return;
    float4 val = ((const float4*)x)[i];
    size_t o = (size_t)seg*(NIN/2) + 2*i;
    ((mha_h2*)h)[o]   = __floats2half2_rn(val.x, val.y);
    ((mha_h2*)h)[o+1] = __floats2half2_rn(val.z, val.w);
}
__global__ void mha_split_w4h(const float* __restrict__ wq, const float* __restrict__ wk,
                              const float* __restrict__ wv, const float* __restrict__ wo,
                              mha_h* __restrict__ h) {
    const size_t NW = (size_t)1024*1024;
    int seg = blockIdx.y;
    const float* x = (seg == 0) ? wq : (seg == 1) ? wk : (seg == 2) ? wv : wo;
    size_t i = (size_t)blockIdx.x*blockDim.x + threadIdx.x;
    if (i >= NW/4) return;
    float4 val = ((const float4*)x)[i];
    size_t o = (size_t)seg*(NW/2) + 2*i;
    ((mha_h2*)h)[o]   = __floats2half2_rn(val.x, val.y);
    ((mha_h2*)h)[o+1] = __floats2half2_rn(val.z, val.w);
}

// ---------------- projection GEMM: C = Xh(M,K) @ Wh(N,K)^T (1 term) ---------
constexpr int EP_HEAD    = 0;   // head-major, hi fp16
constexpr int EP_V_HEADT = 2;   // transposed head-major, hi fp16
constexpr int EP_OUT     = 4;   // fp32 + bias

__device__ __forceinline__ uint32_t mha_swz(int row, int kc) {
    return (uint32_t)(row*64 + ((kc ^ ((row >> 1) & 3)) << 4));
}

template<int BM, int BN>
__device__ __forceinline__ void mha_issue(
    uint32_t s0, int tid, int bm, int bn, int kk, int K,
    const mha_h* pAh, const mha_h* pBh)
{
    constexpr int ABYTES = BM * 64;
    #pragma unroll
    for (int c = tid; c < BM*4; c += 256) {
        int row = c >> 2, kc = c & 3;
        uint32_t off = mha_swz(row, kc);
        size_t g = (size_t)(bm + row) * K + kk + kc*8;
        mha_cpa16(s0 + off, pAh + g);
    }
    #pragma unroll
    for (int c = tid; c < BN*4; c += 256) {
        int row = c >> 2, kc = c & 3;
        uint32_t off = mha_swz(row, kc);
        size_t g = (size_t)(bn + row) * K + kk + kc*8;
        mha_cpa16(s0 + ABYTES + off, pBh + g);
    }
}

template<int BM, int BN, int WSM, int WSN, int MODE>
__global__ void __launch_bounds__(256, 2) mha_gemm(
    const mha_h* __restrict__ Ah, const mha_h* __restrict__ Bh,
    const float* __restrict__ bias,
    float* __restrict__ Cf, mha_h* __restrict__ Ch,
    int M, int N, int K)
{
    constexpr int WM = BM / WSM, WN = BN / WSN;
    constexpr int MT = WM / 16,  NT = WN / 8;
    constexpr int ABYTES = BM * 64;
    constexpr int BBYTES = BN * 64;
    constexpr int STAGE  = ABYTES + BBYTES;

    extern __shared__ char smem[];
    uint32_t sbase = (uint32_t)__cvta_generic_to_shared(smem);

    int tid  = threadIdx.x;
    int warp = tid >> 5, lane = tid & 31;
    int wm = warp / WSN, wn = warp % WSN;
    int bm = blockIdx.y * BM, bn = blockIdx.x * BN;

    float acc[MT][NT][4];
    #pragma unroll
    for (int i = 0; i < MT; i++)
        #pragma unroll
        for (int j = 0; j < NT; j++)
            #pragma unroll
            for (int r = 0; r < 4; r++) acc[i][j][r] = 0.f;

    int ITERS = K / 32;
    mha_issue<BM,BN>(sbase, tid, bm, bn, 0, K, Ah, Bh);
    mha_cp_commit();

    for (int it = 0; it < ITERS; it++) {
        if (it + 1 < ITERS)
            mha_issue<BM,BN>(sbase + ((it+1)&1)*STAGE, tid, bm, bn, (it+1)*32, K,
                             Ah, Bh);
        mha_cp_commit();
        mha_cp_wait<1>(); __syncthreads();

        uint32_t sAh0 = sbase + (it&1)*STAGE;
        uint32_t sBh0 = sAh0 + ABYTES;

        #pragma unroll
        for (int ks = 0; ks < 2; ks++) {
            int kc0 = ks * 2;
            uint32_t fah[MT][4], fbh[NT][2];
            #pragma unroll
            for (int mt = 0; mt < MT; mt++) {
                int r  = wm*WM + mt*16 + (lane & 15);
                int kc = kc0 + (lane >> 4);
                uint32_t off = mha_swz(r, kc);
                mha_ldsm4(fah[mt][0],fah[mt][1],fah[mt][2],fah[mt][3], sAh0 + off);
            }
            #pragma unroll
            for (int g = 0; g < NT/2; g++) {
                int r  = wn*WN + g*16 + (lane & 15);
                int kc = kc0 + (lane >> 4);
                uint32_t off = mha_swz(r, kc);
                uint32_t t0,t1,t2,t3;
                mha_ldsm4(t0,t1,t2,t3, sBh0 + off);
                fbh[2*g][0]=t0; fbh[2*g][1]=t2; fbh[2*g+1][0]=t1; fbh[2*g+1][1]=t3;
            }
            #pragma unroll
            for (int mt = 0; mt < MT; mt++)
                #pragma unroll
                for (int nt = 0; nt < NT; nt++)
                    mha_mma(acc[mt][nt], fah[mt], fbh[nt]);
        }
        __syncthreads();
    }

    #pragma unroll
    for (int mt = 0; mt < MT; mt++)
        #pragma unroll
        for (int nt = 0; nt < NT; nt++) {
            int r0 = bm + wm*WM + mt*16 + (lane >> 2);
            int c0 = bn + wn*WN + nt*8  + (lane & 3)*2;
            #pragma unroll
            for (int half = 0; half < 2; half++) {
                int r = r0 + half*8;
                float v0 = acc[mt][nt][2*half], v1 = acc[mt][nt][2*half+1];
                if (MODE == EP_OUT) {
                    float2 o = make_float2(v0 + bias[c0], v1 + bias[c0+1]);
                    *(float2*)(Cf + (size_t)r*N + c0) = o;
                } else if (MODE == EP_HEAD) {
                    v0 += bias[c0]; v1 += bias[c0+1];
                    int b = r >> 11, s = r & (MHA_S-1);
                    int h = c0 >> 6, dk = c0 & 63;
                    size_t idx = (((size_t)(b*MHA_H + h))*MHA_S + s)*MHA_DK + dk;
                    *(mha_h2*)(Ch + idx) = __floats2half2_rn(v0, v1);
                } else { // EP_V_HEADT
                    v0 += bias[c0]; v1 += bias[c0+1];
                    int b = r >> 11, s = r & (MHA_S-1);
                    int h = c0 >> 6, dk = c0 & 63;
                    size_t idx = (((size_t)(b*MHA_H + h))*MHA_DK + dk)*MHA_S + s;
                    Ch[idx]         = __float2half_rn(v0);
                    Ch[idx + MHA_S] = __float2half_rn(v1);
                }
            }
        }
}

// =================== fused flash attention (hi-only scores) ==================
// Pass 1: qh·kh scores -> row sums of exp(S).
// Pass 2: same scores, P = exp(S)*inv, write P, O += P·Vh.
constexpr int FS_QB    = 128*128;            // Q hi 16KB
constexpr int FS_KB    = 128*128;            // K hi 16KB
constexpr int FS_VB    = 64*256;             // V hi 16KB
constexpr int FS_STAGE = FS_KB + FS_VB;      // 32KB
constexpr int FS_SMEM  = FS_QB + 2*FS_STAGE; // 80KB

__device__ __forceinline__ uint32_t fs_swzk(int row, int c) {
    return (uint32_t)(row*128 + ((c ^ (row & 7)) << 4));
}
__device__ __forceinline__ uint32_t fs_swzv(int row, int c) {
    return (uint32_t)(row*256 + ((c ^ (row & 7)) << 4));
}

__device__ __forceinline__ void fs_loadQ(uint32_t qb, int tid, int bh, int q0,
                                         const mha_h* Qh) {
    #pragma unroll
    for (int i = tid; i < 1024; i += 256) {
        int row = i >> 3, c = i & 7;
        uint32_t off = fs_swzk(row, c);
        size_t g = ((size_t)bh*MHA_S + q0 + row)*MHA_DK + c*8;
        mha_cpa16(qb + off, Qh + g);
    }
}
__device__ __forceinline__ void fs_loadK(uint32_t sb, int tid, int bh, int t,
                                         const mha_h* Kh) {
    #pragma unroll
    for (int i = tid; i < 1024; i += 256) {
        int row = i >> 3, c = i & 7;
        uint32_t off = fs_swzk(row, c);
        size_t g = ((size_t)bh*MHA_S + t*128 + row)*MHA_DK + c*8;
        mha_cpa16(sb + off, Kh + g);
    }
}
__device__ __forceinline__ void fs_loadV(uint32_t sb, int tid, int bh, int t,
                                         const mha_h* Vh) {
    #pragma unroll
    for (int i = tid; i < 1024; i += 256) {
        int row = i >> 4, c = i & 15;
        uint32_t off = fs_swzv(row, c);
        size_t g = ((size_t)bh*MHA_DK + row)*MHA_S + t*128 + c*8;
        mha_cpa16(sb + FS_KB + off, Vh + g);
    }
}

// hi-only 16x64 score half-tile, scaled by 1/8
__device__ __forceinline__ void fs_scores_hi(
    float acc[8][4], uint32_t kbase, int hf, int lane, const uint32_t qh[4][4])
{
    #pragma unroll
    for (int nt = 0; nt < 8; nt++)
        #pragma unroll
        for (int r = 0; r < 4; r++) acc[nt][r] = 0.f;
    #pragma unroll
    for (int j = 0; j < 4; j++) {
        uint32_t kh[8][2];
        #pragma unroll
        for (int g = 0; g < 4; g++) {
            int r = hf*64 + g*16 + (lane & 15);
            int c = 2*j + (lane >> 4);
            uint32_t off = fs_swzk(r, c);
            uint32_t t0,t1,t2,t3;
            mha_ldsm4(t0,t1,t2,t3, kbase + off);
            kh[2*g][0]=t0; kh[2*g][1]=t2; kh[2*g+1][0]=t1; kh[2*g+1][1]=t3;
        }
        #pragma unroll
        for (int nt = 0; nt < 8; nt++)
            mha_mma(acc[nt], qh[j], kh[nt]);
    }
    #pragma unroll
    for (int nt = 0; nt < 8; nt++)
        #pragma unroll
        for (int r = 0; r < 4; r++) acc[nt][r] *= 0.125f;
}

__global__ void __launch_bounds__(256) mha_flash(
    const mha_h* __restrict__ Qh, const mha_h* __restrict__ Kh,
    const mha_h* __restrict__ Vh,
    float* __restrict__ attn, mha_h* __restrict__ Oh)
{
    extern __shared__ char smem[];
    uint32_t sbase = (uint32_t)__cvta_generic_to_shared(smem);
    uint32_t qb  = sbase;
    uint32_t stg = sbase + FS_QB;

    int tid = threadIdx.x;
    int warp = tid >> 5, lane = tid & 31;
    int bh = blockIdx.y;
    int q0 = blockIdx.x * 128;

    uint32_t qfh[4][4];
    float s0 = 0.f, s1 = 0.f;

    // ---- pass 1: scores -> row sums of exp(S) ----
    fs_loadQ(qb, tid, bh, q0, Qh);
    fs_loadK(stg, tid, bh, 0, Kh);
    mha_cp_commit();

    for (int t = 0; t < 16; t++) {
        if (t + 1 < 16) fs_loadK(stg + ((t+1)&1)*FS_STAGE, tid, bh, t+1, Kh);
        mha_cp_commit();
        mha_cp_wait<1>(); __syncthreads();

        if (t == 0) {
            #pragma unroll
            for (int j = 0; j < 4; j++) {
                int r = warp*16 + (lane & 15);
                int c = 2*j + (lane >> 4);
                uint32_t off = fs_swzk(r, c);
                mha_ldsm4(qfh[j][0],qfh[j][1],qfh[j][2],qfh[j][3], qb + off);
            }
        }

        uint32_t kb = stg + (t&1)*FS_STAGE;
        #pragma unroll
        for (int hf = 0; hf < 2; hf++) {
            float acc[8][4];
            fs_scores_hi(acc, kb, hf, lane, qfh);
            #pragma unroll
            for (int nt = 0; nt < 8; nt++) {
                s0 += __expf(acc[nt][0]) + __expf(acc[nt][1]);
                s1 += __expf(acc[nt][2]) + __expf(acc[nt][3]);
            }
        }
        __syncthreads();
    }

    s0 += __shfl_xor_sync(0xffffffffu, s0, 1);
    s0 += __shfl_xor_sync(0xffffffffu, s0, 2);
    s1 += __shfl_xor_sync(0xffffffffu, s1, 1);
    s1 += __shfl_xor_sync(0xffffffffu, s1, 2);
    float inv0 = 1.f / s0, inv1 = 1.f / s1;

    float oacc[8][4];
    #pragma unroll
    for (int nd = 0; nd < 8; nd++)
        #pragma unroll
        for (int r = 0; r < 4; r++) oacc[nd][r] = 0.f;

    // ---- pass 2: recompute scores, P = exp(S)*inv, write P, O += P·Vh ----
    fs_loadK(stg, tid, bh, 0, Kh);
    fs_loadV(stg, tid, bh, 0, Vh);
    mha_cp_commit();

    int qrow0 = q0 + warp*16 + (lane >> 2);
    for (int t = 0; t < 16; t++) {
        if (t + 1 < 16) {
            fs_loadK(stg + ((t+1)&1)*FS_STAGE, tid, bh, t+1, Kh);
            fs_loadV(stg + ((t+1)&1)*FS_STAGE, tid, bh, t+1, Vh);
        }
        mha_cp_commit();
        mha_cp_wait<1>(); __syncthreads();

        uint32_t kb = stg + (t&1)*FS_STAGE;
        #pragma unroll
        for (int hf = 0; hf < 2; hf++) {
            float acc[8][4];
            fs_scores_hi(acc, kb, hf, lane, qfh);
            #pragma unroll
            for (int nt = 0; nt < 8; nt++) {
                acc[nt][0] = __expf(acc[nt][0])*inv0;
                acc[nt][1] = __expf(acc[nt][1])*inv0;
                acc[nt][2] = __expf(acc[nt][2])*inv1;
                acc[nt][3] = __expf(acc[nt][3])*inv1;
            }
            {
                size_t rb0 = ((size_t)bh*MHA_S + qrow0)    *MHA_S + t*128 + hf*64 + (lane&3)*2;
                size_t rb1 = ((size_t)bh*MHA_S + qrow0 + 8)*MHA_S + t*128 + hf*64 + (lane&3)*2;
                #pragma unroll
                for (int nt = 0; nt < 8; nt++) {
                    *(float2*)(attn + rb0 + nt*8) = make_float2(acc[nt][0], acc[nt][1]);
                    *(float2*)(attn + rb1 + nt*8) = make_float2(acc[nt][2], acc[nt][3]);
                }
            }
            #pragma unroll
            for (int kk = 0; kk < 4; kk++) {
                uint32_t pah[4];
                pah[0] = mha_pack(acc[2*kk][0],   acc[2*kk][1]);
                pah[1] = mha_pack(acc[2*kk][2],   acc[2*kk][3]);
                pah[2] = mha_pack(acc[2*kk+1][0], acc[2*kk+1][1]);
                pah[3] = mha_pack(acc[2*kk+1][2], acc[2*kk+1][3]);

                uint32_t vbh[8][2];
                #pragma unroll
                for (int g = 0; g < 4; g++) {
                    int r = g*16 + (lane & 15);
                    int c = 2*(hf*4 + kk) + (lane >> 4);
                    uint32_t off = fs_swzv(r, c);
                    uint32_t t0,t1,t2,t3;
                    mha_ldsm4(t0,t1,t2,t3, kb + FS_KB + off);
                    vbh[2*g][0]=t0; vbh[2*g][1]=t2; vbh[2*g+1][0]=t1; vbh[2*g+1][1]=t3;
                }
                #pragma unroll
                for (int nd = 0; nd < 8; nd++)
                    mha_mma(oacc[nd], pah, vbh[nd]);
            }
        }
        __syncthreads();
    }

    // ---- O epilogue: hi fp16 [b][s][d] ----
    int b = bh >> 4, h = bh & 15;
    #pragma unroll
    for (int nd = 0; nd < 8; nd++) {
        int dk = nd*8 + (lane & 3)*2;
        size_t i0 = ((size_t)(b*MHA_S + qrow0))    *MHA_D + h*MHA_DK + dk;
        size_t i1 = ((size_t)(b*MHA_S + qrow0 + 8))*MHA_D + h*MHA_DK + dk;
        *(mha_h2*)(Oh + i0) = __floats2half2_rn(oacc[nd][0], oacc[nd][1]);
        *(mha_h2*)(Oh + i1) = __floats2half2_rn(oacc[nd][2], oacc[nd][3]);
    }
}

// ---------------- host ----------------
extern "C" void kernel_launch(void* const* d_in, const int* in_sizes, int n_in,
                              void* d_out, int out_size)
{
    (void)in_sizes; (void)n_in; (void)out_size;
    const float* q  = (const float*)d_in[0];
    const float* k  = (const float*)d_in[1];
    const float* v  = (const float*)d_in[2];
    const float* wq = (const float*)d_in[3];
    const float* bq = (const float*)d_in[4];
    const float* wk = (const float*)d_in[5];
    const float* bk = (const float*)d_in[6];
    const float* wv = (const float*)d_in[7];
    const float* bv = (const float*)d_in[8];
    const float* wo = (const float*)d_in[9];
    const float* bo = (const float*)d_in[10];

    float* out  = (float*)d_out;
    float* attn = out + (size_t)MHA_B * MHA_S * MHA_D;

    mha_h *inh, *wh, *Qh, *Kh, *Vth, *Oh;
    cudaGetSymbolAddress((void**)&inh, g_inh);
    cudaGetSymbolAddress((void**)&wh,  g_wh);
    cudaGetSymbolAddress((void**)&Qh,  g_Qh);
    cudaGetSymbolAddress((void**)&Kh,  g_Kh);
    cudaGetSymbolAddress((void**)&Vth, g_Vth);
    cudaGetSymbolAddress((void**)&Oh,  g_Oh);

    const size_t NIN = (size_t)8192*1024;
    const size_t NW  = (size_t)1024*1024;

    mha_split_in3<<<dim3((unsigned)(NIN/4/256), 3), 256>>>(q, k, v, inh);
    mha_split_w4h<<<dim3((unsigned)(NW/4/256),  4), 256>>>(wq, wk, wv, wo, wh);

    auto gqk = mha_gemm<128,128,2,4,EP_HEAD>;      // Q and K
    auto gv2 = mha_gemm<128,128,2,4,EP_V_HEADT>;
    auto gou = mha_gemm<128,128,2,4,EP_OUT>;

    const int SM1 = 2 * (128*64 + 128*64);   // 32768 B
    cudaFuncSetAttribute(gqk, cudaFuncAttributeMaxDynamicSharedMemorySize, SM1);
    cudaFuncSetAttribute(gv2, cudaFuncAttributeMaxDynamicSharedMemorySize, SM1);
    cudaFuncSetAttribute(gou, cudaFuncAttributeMaxDynamicSharedMemorySize, SM1);
    cudaFuncSetAttribute(mha_flash, cudaFuncAttributeMaxDynamicSharedMemorySize, FS_SMEM);

    dim3 t(256);

    dim3 gproj(1024/128, 8192/128, 1);
    gqk<<<gproj, t, SM1>>>(inh,         wh,        bq, nullptr, Qh,  8192, 1024, 1024);
    gqk<<<gproj, t, SM1>>>(inh + NIN,   wh + NW,   bk, nullptr, Kh,  8192, 1024, 1024);
    gv2<<<gproj, t, SM1>>>(inh + 2*NIN, wh + 2*NW, bv, nullptr, Vth, 8192, 1024, 1024);

    dim3 gf(16, MHA_B*MHA_H);
    mha_flash<<<gf, t, FS_SMEM>>>(Qh, Kh, Vth, attn, Oh);

    gou<<<gproj, t, SM1>>>(Oh, wh + 3*NW, bo, out, nullptr, 8192, 1024, 1024);
}

// round 14
// speedup vs baseline: 1.7728x; 1.0441x over previous
#include <cuda_runtime.h>
#include <cuda_fp16.h>
#include <cstdint>
#include <cstddef>

typedef __half  mha_h;
typedef __half2 mha_h2;

constexpr int MHA_B  = 4;
constexpr int MHA_S  = 2048;
constexpr int MHA_D  = 1024;
constexpr int MHA_H  = 16;
constexpr int MHA_DK = 64;

// ---------------- scratch ----------------
__device__ mha_h g_inh[(size_t)3*8192*1024];                     // input hi
__device__ mha_h g_wh [(size_t)4*1024*1024];                     // weight hi
__device__ mha_h g_Qh[(size_t)8388608];                          // [bh][s][dk] hi
__device__ mha_h g_Kh[(size_t)8388608];                          // [bh][s][dk] hi
__device__ mha_h g_Vth[(size_t)8388608];                         // [bh][dk][s] hi
__device__ mha_h g_Oh[(size_t)8388608];                          // [b][s][d] hi

// ---------------- PTX helpers ----------------
__device__ __forceinline__ void mha_cpa16(uint32_t dst, const void* src) {
    asm volatile("cp.async.cg.shared.global [%0], [%1], 16;\n" :: "r"(dst), "l"(src));
}
__device__ __forceinline__ void mha_cp_commit() { asm volatile("cp.async.commit_group;\n"); }
template<int N> __device__ __forceinline__ void mha_cp_wait() {
    asm volatile("cp.async.wait_group %0;\n" :: "n"(N));
}
__device__ __forceinline__ void mha_ldsm4(uint32_t &r0, uint32_t &r1, uint32_t &r2,
                                          uint32_t &r3, uint32_t addr) {
    asm volatile("ldmatrix.sync.aligned.m8n8.x4.shared.b16 {%0,%1,%2,%3}, [%4];\n"
        : "=r"(r0),"=r"(r1),"=r"(r2),"=r"(r3) : "r"(addr));
}
__device__ __forceinline__ void mha_mma(float* d, const uint32_t* a, const uint32_t* b) {
    asm volatile("mma.sync.aligned.m16n8k16.row.col.f32.f16.f16.f32 "
      "{%0,%1,%2,%3}, {%4,%5,%6,%7}, {%8,%9}, {%0,%1,%2,%3};\n"
      : "+f"(d[0]),"+f"(d[1]),"+f"(d[2]),"+f"(d[3])
      : "r"(a[0]),"r"(a[1]),"r"(a[2]),"r"(a[3]),"r"(b[0]),"r"(b[1]));
}
__device__ __forceinline__ uint32_t mha_pack(float a, float b) {
    mha_h2 t = __floats2half2_rn(a, b);
    return *(uint32_t*)&t;
}

// ---------------- input/weight split (hi only) ----------------
__global__ void mha_split_in3(const float* __restrict__ q, const float* __restrict__ k,
                              const float* __restrict__ v, mha_h* __restrict__ h) {
    const size_t NIN = (size_t)8192*1024;
    int seg = blockIdx.y;
    const float* x = (seg == 0) ? q : (seg == 1) ? k : v;
    size_t i = (size_t)blockIdx.x*blockDim.x + threadIdx.x;
    if (i >= NIN/4) return;
    float4 val = ((const float4*)x)[i];
    size_t o = (size_t)seg*(NIN/2) + 2*i;
    ((mha_h2*)h)[o]   = __floats2half2_rn(val.x, val.y);
    ((mha_h2*)h)[o+1] = __floats2half2_rn(val.z, val.w);
}
__global__ void mha_split_w4h(const float* __restrict__ wq, const float* __restrict__ wk,
                              const float* __restrict__ wv, const float* __restrict__ wo,
                              mha_h* __restrict__ h) {
    const size_t NW = (size_t)1024*1024;
    int seg = blockIdx.y;
    const float* x = (seg == 0) ? wq : (seg == 1) ? wk : (seg == 2) ? wv : wo;
    size_t i = (size_t)blockIdx.x*blockDim.x + threadIdx.x;
    if (i >= NW/4) return;
    float4 val = ((const float4*)x)[i];
    size_t o = (size_t)seg*(NW/2) + 2*i;
    ((mha_h2*)h)[o]   = __floats2half2_rn(val.x, val.y);
    ((mha_h2*)h)[o+1] = __floats2half2_rn(val.z, val.w);
}

// ---------------- projection GEMM: C = Xh(M,K) @ Wh(N,K)^T (1 term) ---------
constexpr int EP_HEAD    = 0;   // head-major, hi fp16
constexpr int EP_V_HEADT = 2;   // transposed head-major, hi fp16
constexpr int EP_OUT     = 4;   // fp32 + bias

__device__ __forceinline__ uint32_t mha_swz(int row, int kc) {
    return (uint32_t)(row*64 + ((kc ^ ((row >> 1) & 3)) << 4));
}

template<int BM, int BN>
__device__ __forceinline__ void mha_issue(
    uint32_t s0, int tid, int bm, int bn, int kk, int K,
    const mha_h* pAh, const mha_h* pBh)
{
    constexpr int ABYTES = BM * 64;
    #pragma unroll
    for (int c = tid; c < BM*4; c += 256) {
        int row = c >> 2, kc = c & 3;
        uint32_t off = mha_swz(row, kc);
        size_t g = (size_t)(bm + row) * K + kk + kc*8;
        mha_cpa16(s0 + off, pAh + g);
    }
    #pragma unroll
    for (int c = tid; c < BN*4; c += 256) {
        int row = c >> 2, kc = c & 3;
        uint32_t off = mha_swz(row, kc);
        size_t g = (size_t)(bn + row) * K + kk + kc*8;
        mha_cpa16(s0 + ABYTES + off, pBh + g);
    }
}

template<int BM, int BN, int WSM, int WSN, int MODE>
__global__ void __launch_bounds__(256, 2) mha_gemm(
    const mha_h* __restrict__ Ah, const mha_h* __restrict__ Bh,
    const float* __restrict__ bias,
    float* __restrict__ Cf, mha_h* __restrict__ Ch,
    int M, int N, int K)
{
    constexpr int WM = BM / WSM, WN = BN / WSN;
    constexpr int MT = WM / 16,  NT = WN / 8;
    constexpr int ABYTES = BM * 64;
    constexpr int BBYTES = BN * 64;
    constexpr int STAGE  = ABYTES + BBYTES;

    extern __shared__ char smem[];
    uint32_t sbase = (uint32_t)__cvta_generic_to_shared(smem);

    int tid  = threadIdx.x;
    int warp = tid >> 5, lane = tid & 31;
    int wm = warp / WSN, wn = warp % WSN;
    int bm = blockIdx.y * BM, bn = blockIdx.x * BN;

    float acc[MT][NT][4];
    #pragma unroll
    for (int i = 0; i < MT; i++)
        #pragma unroll
        for (int j = 0; j < NT; j++)
            #pragma unroll
            for (int r = 0; r < 4; r++) acc[i][j][r] = 0.f;

    int ITERS = K / 32;
    mha_issue<BM,BN>(sbase, tid, bm, bn, 0, K, Ah, Bh);
    mha_cp_commit();

    for (int it = 0; it < ITERS; it++) {
        if (it + 1 < ITERS)
            mha_issue<BM,BN>(sbase + ((it+1)&1)*STAGE, tid, bm, bn, (it+1)*32, K,
                             Ah, Bh);
        mha_cp_commit();
        mha_cp_wait<1>(); __syncthreads();

        uint32_t sAh0 = sbase + (it&1)*STAGE;
        uint32_t sBh0 = sAh0 + ABYTES;

        #pragma unroll
        for (int ks = 0; ks < 2; ks++) {
            int kc0 = ks * 2;
            uint32_t fah[MT][4], fbh[NT][2];
            #pragma unroll
            for (int mt = 0; mt < MT; mt++) {
                int r  = wm*WM + mt*16 + (lane & 15);
                int kc = kc0 + (lane >> 4);
                uint32_t off = mha_swz(r, kc);
                mha_ldsm4(fah[mt][0],fah[mt][1],fah[mt][2],fah[mt][3], sAh0 + off);
            }
            #pragma unroll
            for (int g = 0; g < NT/2; g++) {
                int r  = wn*WN + g*16 + (lane & 15);
                int kc = kc0 + (lane >> 4);
                uint32_t off = mha_swz(r, kc);
                uint32_t t0,t1,t2,t3;
                mha_ldsm4(t0,t1,t2,t3, sBh0 + off);
                fbh[2*g][0]=t0; fbh[2*g][1]=t2; fbh[2*g+1][0]=t1; fbh[2*g+1][1]=t3;
            }
            #pragma unroll
            for (int mt = 0; mt < MT; mt++)
                #pragma unroll
                for (int nt = 0; nt < NT; nt++)
                    mha_mma(acc[mt][nt], fah[mt], fbh[nt]);
        }
        __syncthreads();
    }

    #pragma unroll
    for (int mt = 0; mt < MT; mt++)
        #pragma unroll
        for (int nt = 0; nt < NT; nt++) {
            int r0 = bm + wm*WM + mt*16 + (lane >> 2);
            int c0 = bn + wn*WN + nt*8  + (lane & 3)*2;
            #pragma unroll
            for (int half = 0; half < 2; half++) {
                int r = r0 + half*8;
                float v0 = acc[mt][nt][2*half], v1 = acc[mt][nt][2*half+1];
                if (MODE == EP_OUT) {
                    float2 o = make_float2(v0 + bias[c0], v1 + bias[c0+1]);
                    *(float2*)(Cf + (size_t)r*N + c0) = o;
                } else if (MODE == EP_HEAD) {
                    v0 += bias[c0]; v1 += bias[c0+1];
                    int b = r >> 11, s = r & (MHA_S-1);
                    int h = c0 >> 6, dk = c0 & 63;
                    size_t idx = (((size_t)(b*MHA_H + h))*MHA_S + s)*MHA_DK + dk;
                    *(mha_h2*)(Ch + idx) = __floats2half2_rn(v0, v1);
                } else { // EP_V_HEADT
                    v0 += bias[c0]; v1 += bias[c0+1];
                    int b = r >> 11, s = r & (MHA_S-1);
                    int h = c0 >> 6, dk = c0 & 63;
                    size_t idx = (((size_t)(b*MHA_H + h))*MHA_DK + dk)*MHA_S + s;
                    Ch[idx]         = __float2half_rn(v0);
                    Ch[idx + MHA_S] = __float2half_rn(v1);
                }
            }
        }
}

// =================== fused flash attention (hi-only scores, 2 CTAs/SM) =======
constexpr int FS_QB    = 128*128;            // Q hi 16KB
constexpr int FS_KB    = 128*128;            // K hi 16KB
constexpr int FS_VB    = 64*256;             // V hi 16KB
constexpr int FS_STAGE = FS_KB + FS_VB;      // 32KB
constexpr int FS_SMEM  = FS_QB + 2*FS_STAGE; // 80KB -> 2 CTAs/SM

__device__ __forceinline__ uint32_t fs_swzk(int row, int c) {
    return (uint32_t)(row*128 + ((c ^ (row & 7)) << 4));
}
__device__ __forceinline__ uint32_t fs_swzv(int row, int c) {
    return (uint32_t)(row*256 + ((c ^ (row & 7)) << 4));
}

__device__ __forceinline__ void fs_loadQ(uint32_t qb, int tid, int bh, int q0,
                                         const mha_h* Qh) {
    #pragma unroll
    for (int i = tid; i < 1024; i += 256) {
        int row = i >> 3, c = i & 7;
        uint32_t off = fs_swzk(row, c);
        size_t g = ((size_t)bh*MHA_S + q0 + row)*MHA_DK + c*8;
        mha_cpa16(qb + off, Qh + g);
    }
}
__device__ __forceinline__ void fs_loadK(uint32_t sb, int tid, int bh, int t,
                                         const mha_h* Kh) {
    #pragma unroll
    for (int i = tid; i < 1024; i += 256) {
        int row = i >> 3, c = i & 7;
        uint32_t off = fs_swzk(row, c);
        size_t g = ((size_t)bh*MHA_S + t*128 + row)*MHA_DK + c*8;
        mha_cpa16(sb + off, Kh + g);
    }
}
__device__ __forceinline__ void fs_loadV(uint32_t sb, int tid, int bh, int t,
                                         const mha_h* Vh) {
    #pragma unroll
    for (int i = tid; i < 1024; i += 256) {
        int row = i >> 4, c = i & 15;
        uint32_t off = fs_swzv(row, c);
        size_t g = ((size_t)bh*MHA_DK + row)*MHA_S + t*128 + c*8;
        mha_cpa16(sb + FS_KB + off, Vh + g);
    }
}

// hi-only 16x64 score half-tile, scaled by 1/8
__device__ __forceinline__ void fs_scores_hi(
    float acc[8][4], uint32_t kbase, int hf, int lane, const uint32_t qh[4][4])
{
    #pragma unroll
    for (int nt = 0; nt < 8; nt++)
        #pragma unroll
        for (int r = 0; r < 4; r++) acc[nt][r] = 0.f;
    #pragma unroll
    for (int j = 0; j < 4; j++) {
        uint32_t kh[8][2];
        #pragma unroll
        for (int g = 0; g < 4; g++) {
            int r = hf*64 + g*16 + (lane & 15);
            int c = 2*j + (lane >> 4);
            uint32_t off = fs_swzk(r, c);
            uint32_t t0,t1,t2,t3;
            mha_ldsm4(t0,t1,t2,t3, kbase + off);
            kh[2*g][0]=t0; kh[2*g][1]=t2; kh[2*g+1][0]=t1; kh[2*g+1][1]=t3;
        }
        #pragma unroll
        for (int nt = 0; nt < 8; nt++)
            mha_mma(acc[nt], qh[j], kh[nt]);
    }
    #pragma unroll
    for (int nt = 0; nt < 8; nt++)
        #pragma unroll
        for (int r = 0; r < 4; r++) acc[nt][r] *= 0.125f;
}

__global__ void __launch_bounds__(256, 2) mha_flash(
    const mha_h* __restrict__ Qh, const mha_h* __restrict__ Kh,
    const mha_h* __restrict__ Vh,
    float* __restrict__ attn, mha_h* __restrict__ Oh)
{
    extern __shared__ char smem[];
    uint32_t sbase = (uint32_t)__cvta_generic_to_shared(smem);
    uint32_t qb  = sbase;
    uint32_t stg = sbase + FS_QB;

    int tid = threadIdx.x;
    int warp = tid >> 5, lane = tid & 31;
    int bh = blockIdx.y;
    int q0 = blockIdx.x * 128;

    uint32_t qfh[4][4];
    float s0 = 0.f, s1 = 0.f;

    // ---- pass 1: scores -> row sums of exp(S) ----
    fs_loadQ(qb, tid, bh, q0, Qh);
    fs_loadK(stg, tid, bh, 0, Kh);
    mha_cp_commit();

    for (int t = 0; t < 16; t++) {
        if (t + 1 < 16) fs_loadK(stg + ((t+1)&1)*FS_STAGE, tid, bh, t+1, Kh);
        mha_cp_commit();
        mha_cp_wait<1>(); __syncthreads();

        if (t == 0) {
            #pragma unroll
            for (int j = 0; j < 4; j++) {
                int r = warp*16 + (lane & 15);
                int c = 2*j + (lane >> 4);
                uint32_t off = fs_swzk(r, c);
                mha_ldsm4(qfh[j][0],qfh[j][1],qfh[j][2],qfh[j][3], qb + off);
            }
        }

        uint32_t kb = stg + (t&1)*FS_STAGE;
        #pragma unroll
        for (int hf = 0; hf < 2; hf++) {
            float acc[8][4];
            fs_scores_hi(acc, kb, hf, lane, qfh);
            #pragma unroll
            for (int nt = 0; nt < 8; nt++) {
                s0 += __expf(acc[nt][0]) + __expf(acc[nt][1]);
                s1 += __expf(acc[nt][2]) + __expf(acc[nt][3]);
            }
        }
        __syncthreads();
    }

    s0 += __shfl_xor_sync(0xffffffffu, s0, 1);
    s0 += __shfl_xor_sync(0xffffffffu, s0, 2);
    s1 += __shfl_xor_sync(0xffffffffu, s1, 1);
    s1 += __shfl_xor_sync(0xffffffffu, s1, 2);
    float inv0 = 1.f / s0, inv1 = 1.f / s1;

    float oacc[8][4];
    #pragma unroll
    for (int nd = 0; nd < 8; nd++)
        #pragma unroll
        for (int r = 0; r < 4; r++) oacc[nd][r] = 0.f;

    // ---- pass 2: recompute scores, P = exp(S)*inv, write P, O += P·Vh ----
    fs_loadK(stg, tid, bh, 0, Kh);
    fs_loadV(stg, tid, bh, 0, Vh);
    mha_cp_commit();

    int qrow0 = q0 + warp*16 + (lane >> 2);
    for (int t = 0; t < 16; t++) {
        if (t + 1 < 16) {
            fs_loadK(stg + ((t+1)&1)*FS_STAGE, tid, bh, t+1, Kh);
            fs_loadV(stg + ((t+1)&1)*FS_STAGE, tid, bh, t+1, Vh);
        }
        mha_cp_commit();
        mha_cp_wait<1>(); __syncthreads();

        uint32_t kb = stg + (t&1)*FS_STAGE;
        #pragma unroll
        for (int hf = 0; hf < 2; hf++) {
            float acc[8][4];
            fs_scores_hi(acc, kb, hf, lane, qfh);
            #pragma unroll
            for (int nt = 0; nt < 8; nt++) {
                acc[nt][0] = __expf(acc[nt][0])*inv0;
                acc[nt][1] = __expf(acc[nt][1])*inv0;
                acc[nt][2] = __expf(acc[nt][2])*inv1;
                acc[nt][3] = __expf(acc[nt][3])*inv1;
            }
            {
                size_t rb0 = ((size_t)bh*MHA_S + qrow0)    *MHA_S + t*128 + hf*64 + (lane&3)*2;
                size_t rb1 = ((size_t)bh*MHA_S + qrow0 + 8)*MHA_S + t*128 + hf*64 + (lane&3)*2;
                #pragma unroll
                for (int nt = 0; nt < 8; nt++) {
                    *(float2*)(attn + rb0 + nt*8) = make_float2(acc[nt][0], acc[nt][1]);
                    *(float2*)(attn + rb1 + nt*8) = make_float2(acc[nt][2], acc[nt][3]);
                }
            }
            #pragma unroll
            for (int kk = 0; kk < 4; kk++) {
                uint32_t pah[4];
                pah[0] = mha_pack(acc[2*kk][0],   acc[2*kk][1]);
                pah[1] = mha_pack(acc[2*kk][2],   acc[2*kk][3]);
                pah[2] = mha_pack(acc[2*kk+1][0], acc[2*kk+1][1]);
                pah[3] = mha_pack(acc[2*kk+1][2], acc[2*kk+1][3]);

                uint32_t vbh[8][2];
                #pragma unroll
                for (int g = 0; g < 4; g++) {
                    int r = g*16 + (lane & 15);
                    int c = 2*(hf*4 + kk) + (lane >> 4);
                    uint32_t off = fs_swzv(r, c);
                    uint32_t t0,t1,t2,t3;
                    mha_ldsm4(t0,t1,t2,t3, kb + FS_KB + off);
                    vbh[2*g][0]=t0; vbh[2*g][1]=t2; vbh[2*g+1][0]=t1; vbh[2*g+1][1]=t3;
                }
                #pragma unroll
                for (int nd = 0; nd < 8; nd++)
                    mha_mma(oacc[nd], pah, vbh[nd]);
            }
        }
        __syncthreads();
    }

    // ---- O epilogue: hi fp16 [b][s][d] ----
    int b = bh >> 4, h = bh & 15;
    #pragma unroll
    for (int nd = 0; nd < 8; nd++) {
        int dk = nd*8 + (lane & 3)*2;
        size_t i0 = ((size_t)(b*MHA_S + qrow0))    *MHA_D + h*MHA_DK + dk;
        size_t i1 = ((size_t)(b*MHA_S + qrow0 + 8))*MHA_D + h*MHA_DK + dk;
        *(mha_h2*)(Oh + i0) = __floats2half2_rn(oacc[nd][0], oacc[nd][1]);
        *(mha_h2*)(Oh + i1) = __floats2half2_rn(oacc[nd][2], oacc[nd][3]);
    }
}

// ---------------- host ----------------
extern "C" void kernel_launch(void* const* d_in, const int* in_sizes, int n_in,
                              void* d_out, int out_size)
{
    (void)in_sizes; (void)n_in; (void)out_size;
    const float* q  = (const float*)d_in[0];
    const float* k  = (const float*)d_in[1];
    const float* v  = (const float*)d_in[2];
    const float* wq = (const float*)d_in[3];
    const float* bq = (const float*)d_in[4];
    const float* wk = (const float*)d_in[5];
    const float* bk = (const float*)d_in[6];
    const float* wv = (const float*)d_in[7];
    const float* bv = (const float*)d_in[8];
    const float* wo = (const float*)d_in[9];
    const float* bo = (const float*)d_in[10];

    float* out  = (float*)d_out;
    float* attn = out + (size_t)MHA_B * MHA_S * MHA_D;

    mha_h *inh, *wh, *Qh, *Kh, *Vth, *Oh;
    cudaGetSymbolAddress((void**)&inh, g_inh);
    cudaGetSymbolAddress((void**)&wh,  g_wh);
    cudaGetSymbolAddress((void**)&Qh,  g_Qh);
    cudaGetSymbolAddress((void**)&Kh,  g_Kh);
    cudaGetSymbolAddress((void**)&Vth, g_Vth);
    cudaGetSymbolAddress((void**)&Oh,  g_Oh);

    const size_t NIN = (size_t)8192*1024;
    const size_t NW  = (size_t)1024*1024;

    mha_split_in3<<<dim3((unsigned)(NIN/4/256), 3), 256>>>(q, k, v, inh);
    mha_split_w4h<<<dim3((unsigned)(NW/4/256),  4), 256>>>(wq, wk, wv, wo, wh);

    auto gqk = mha_gemm<128,128,2,4,EP_HEAD>;      // Q and K
    auto gv2 = mha_gemm<128,128,2,4,EP_V_HEADT>;
    auto gou = mha_gemm<128,128,2,4,EP_OUT>;

    const int SM1 = 2 * (128*64 + 128*64);   // 32768 B
    cudaFuncSetAttribute(gqk, cudaFuncAttributeMaxDynamicSharedMemorySize, SM1);
    cudaFuncSetAttribute(gv2, cudaFuncAttributeMaxDynamicSharedMemorySize, SM1);
    cudaFuncSetAttribute(gou, cudaFuncAttributeMaxDynamicSharedMemorySize, SM1);
    cudaFuncSetAttribute(mha_flash, cudaFuncAttributeMaxDynamicSharedMemorySize, FS_SMEM);

    dim3 t(256);

    dim3 gproj(1024/128, 8192/128, 1);
    gqk<<<gproj, t, SM1>>>(inh,         wh,        bq, nullptr, Qh,  8192, 1024, 1024);
    gqk<<<gproj, t, SM1>>>(inh + NIN,   wh + NW,   bk, nullptr, Kh,  8192, 1024, 1024);
    gv2<<<gproj, t, SM1>>>(inh + 2*NIN, wh + 2*NW, bv, nullptr, Vth, 8192, 1024, 1024);

    dim3 gf(16, MHA_B*MHA_H);
    mha_flash<<<gf, t, FS_SMEM>>>(Qh, Kh, Vth, attn, Oh);

    gou<<<gproj, t, SM1>>>(Oh, wh + 3*NW, bo, out, nullptr, 8192, 1024, 1024);
}

// round 15
// speedup vs baseline: 1.8785x; 1.0596x over previous
#include <cuda_runtime.h>
#include <cuda_fp16.h>
#include <cstdint>
#include <cstddef>

typedef __half  mha_h;
typedef __half2 mha_h2;

constexpr int MHA_B  = 4;
constexpr int MHA_S  = 2048;
constexpr int MHA_D  = 1024;
constexpr int MHA_H  = 16;
constexpr int MHA_DK = 64;

// ---------------- scratch ----------------
__device__ mha_h g_inh[(size_t)3*8192*1024];                     // input hi
__device__ mha_h g_wh [(size_t)4*1024*1024];                     // weight hi
__device__ mha_h g_Qh[(size_t)8388608];                          // [bh][s][dk] hi
__device__ mha_h g_Kh[(size_t)8388608];                          // [bh][s][dk] hi
__device__ mha_h g_Vth[(size_t)8388608];                         // [bh][dk][s] hi
__device__ mha_h g_Oh[(size_t)8388608];                          // [b][s][d] hi
__device__ float g_inv[(size_t)64*2048];                         // 1/rowsum

// ---------------- PTX helpers ----------------
__device__ __forceinline__ void mha_cpa16(uint32_t dst, const void* src) {
    asm volatile("cp.async.cg.shared.global [%0], [%1], 16;\n" :: "r"(dst), "l"(src));
}
__device__ __forceinline__ void mha_cp_commit() { asm volatile("cp.async.commit_group;\n"); }
template<int N> __device__ __forceinline__ void mha_cp_wait() {
    asm volatile("cp.async.wait_group %0;\n" :: "n"(N));
}
__device__ __forceinline__ void mha_ldsm4(uint32_t &r0, uint32_t &r1, uint32_t &r2,
                                          uint32_t &r3, uint32_t addr) {
    asm volatile("ldmatrix.sync.aligned.m8n8.x4.shared.b16 {%0,%1,%2,%3}, [%4];\n"
        : "=r"(r0),"=r"(r1),"=r"(r2),"=r"(r3) : "r"(addr));
}
__device__ __forceinline__ void mha_mma(float* d, const uint32_t* a, const uint32_t* b) {
    asm volatile("mma.sync.aligned.m16n8k16.row.col.f32.f16.f16.f32 "
      "{%0,%1,%2,%3}, {%4,%5,%6,%7}, {%8,%9}, {%0,%1,%2,%3};\n"
      : "+f"(d[0]),"+f"(d[1]),"+f"(d[2]),"+f"(d[3])
      : "r"(a[0]),"r"(a[1]),"r"(a[2]),"r"(a[3]),"r"(b[0]),"r"(b[1]));
}
__device__ __forceinline__ uint32_t mha_pack(float a, float b) {
    mha_h2 t = __floats2half2_rn(a, b);
    return *(uint32_t*)&t;
}

// ---------------- input/weight split (hi only) ----------------
__global__ void mha_split_in3(const float* __restrict__ q, const float* __restrict__ k,
                              const float* __restrict__ v, mha_h* __restrict__ h) {
    const size_t NIN = (size_t)8192*1024;
    int seg = blockIdx.y;
    const float* x = (seg == 0) ? q : (seg == 1) ? k : v;
    size_t i = (size_t)blockIdx.x*blockDim.x + threadIdx.x;
    if (i >= NIN/4) return;
    float4 val = ((const float4*)x)[i];
    size_t o = (size_t)seg*(NIN/2) + 2*i;
    ((mha_h2*)h)[o]   = __floats2half2_rn(val.x, val.y);
    ((mha_h2*)h)[o+1] = __floats2half2_rn(val.z, val.w);
}
__global__ void mha_split_w4h(const float* __restrict__ wq, const float* __restrict__ wk,
                              const float* __restrict__ wv, const float* __restrict__ wo,
                              mha_h* __restrict__ h) {
    const size_t NW = (size_t)1024*1024;
    int seg = blockIdx.y;
    const float* x = (seg == 0) ? wq : (seg == 1) ? wk : (seg == 2) ? wv : wo;
    size_t i = (size_t)blockIdx.x*blockDim.x + threadIdx.x;
    if (i >= NW/4) return;
    float4 val = ((const float4*)x)[i];
    size_t o = (size_t)seg*(NW/2) + 2*i;
    ((mha_h2*)h)[o]   = __floats2half2_rn(val.x, val.y);
    ((mha_h2*)h)[o+1] = __floats2half2_rn(val.z, val.w);
}

// ---------------- projection GEMM core pieces ----------------
__device__ __forceinline__ uint32_t mha_swz(int row, int kc) {
    return (uint32_t)(row*64 + ((kc ^ ((row >> 1) & 3)) << 4));
}

// stage: A (128*64B) + B (128*64B)
__device__ __forceinline__ void mha_issue(
    uint32_t s0, int tid, int bm, int bn, int kk,
    const mha_h* pAh, const mha_h* pBh)
{
    constexpr int K = 1024;
    constexpr int ABYTES = 128 * 64;
    #pragma unroll
    for (int c = tid; c < 512; c += 256) {
        int row = c >> 2, kc = c & 3;
        uint32_t off = mha_swz(row, kc);
        size_t g = (size_t)(bm + row) * K + kk + kc*8;
        mha_cpa16(s0 + off, pAh + g);
    }
    #pragma unroll
    for (int c = tid; c < 512; c += 256) {
        int row = c >> 2, kc = c & 3;
        uint32_t off = mha_swz(row, kc);
        size_t g = (size_t)(bn + row) * K + kk + kc*8;
        mha_cpa16(s0 + ABYTES + off, pBh + g);
    }
}

// GEMM mainloop: 128x128 tile, K=1024, acc in regs. Returns in acc.
__device__ __forceinline__ void mha_gemm_core(
    uint32_t sbase, int tid, int warp, int lane, int bm, int bn,
    const mha_h* Ah, const mha_h* Bh, float acc[4][4][4])
{
    constexpr int ABYTES = 128 * 64;
    constexpr int STAGE  = 2 * ABYTES;
    int wm = warp >> 2, wn = warp & 3;     // WSM=2, WSN=4 -> WM=64, WN=32

    #pragma unroll
    for (int i = 0; i < 4; i++)
        #pragma unroll
        for (int j = 0; j < 4; j++)
            #pragma unroll
            for (int r = 0; r < 4; r++) acc[i][j][r] = 0.f;

    mha_issue(sbase, tid, bm, bn, 0, Ah, Bh);
    mha_cp_commit();

    for (int it = 0; it < 32; it++) {
        if (it + 1 < 32)
            mha_issue(sbase + ((it+1)&1)*STAGE, tid, bm, bn, (it+1)*32, Ah, Bh);
        mha_cp_commit();
        mha_cp_wait<1>(); __syncthreads();

        uint32_t sAh0 = sbase + (it&1)*STAGE;
        uint32_t sBh0 = sAh0 + ABYTES;

        #pragma unroll
        for (int ks = 0; ks < 2; ks++) {
            int kc0 = ks * 2;
            uint32_t fah[4][4], fbh[4][2];
            #pragma unroll
            for (int mt = 0; mt < 4; mt++) {
                int r  = wm*64 + mt*16 + (lane & 15);
                int kc = kc0 + (lane >> 4);
                mha_ldsm4(fah[mt][0],fah[mt][1],fah[mt][2],fah[mt][3],
                          sAh0 + mha_swz(r, kc));
            }
            #pragma unroll
            for (int g = 0; g < 2; g++) {
                int r  = wn*32 + g*16 + (lane & 15);
                int kc = kc0 + (lane >> 4);
                uint32_t t0,t1,t2,t3;
                mha_ldsm4(t0,t1,t2,t3, sBh0 + mha_swz(r, kc));
                fbh[2*g][0]=t0; fbh[2*g][1]=t2; fbh[2*g+1][0]=t1; fbh[2*g+1][1]=t3;
            }
            #pragma unroll
            for (int mt = 0; mt < 4; mt++)
                #pragma unroll
                for (int nt = 0; nt < 4; nt++)
                    mha_mma(acc[mt][nt], fah[mt], fbh[nt]);
        }
        __syncthreads();
    }
}

// merged Q/K/V projection: z selects input slab, weight slab, bias, epilogue
__global__ void __launch_bounds__(256, 2) mha_gemm_qkv(
    const mha_h* __restrict__ inh, const mha_h* __restrict__ wh,
    const float* __restrict__ bq, const float* __restrict__ bk,
    const float* __restrict__ bv,
    mha_h* __restrict__ Qh, mha_h* __restrict__ Kh, mha_h* __restrict__ Vth)
{
    extern __shared__ char smem[];
    uint32_t sbase = (uint32_t)__cvta_generic_to_shared(smem);
    int tid = threadIdx.x, warp = tid >> 5, lane = tid & 31;
    int bm = blockIdx.y * 128, bn = blockIdx.x * 128;
    int z = blockIdx.z;

    const size_t NIN = (size_t)8192*1024;
    const size_t NW  = (size_t)1024*1024;
    const mha_h* Ah = inh + (size_t)z*NIN;
    const mha_h* Bh = wh  + (size_t)z*NW;
    const float* bias = (z == 0) ? bq : (z == 1) ? bk : bv;
    mha_h* Ch = (z == 0) ? Qh : (z == 1) ? Kh : Vth;

    float acc[4][4][4];
    mha_gemm_core(sbase, tid, warp, lane, bm, bn, Ah, Bh, acc);

    int wm = warp >> 2, wn = warp & 3;
    #pragma unroll
    for (int mt = 0; mt < 4; mt++)
        #pragma unroll
        for (int nt = 0; nt < 4; nt++) {
            int r0 = bm + wm*64 + mt*16 + (lane >> 2);
            int c0 = bn + wn*32 + nt*8  + (lane & 3)*2;
            #pragma unroll
            for (int half = 0; half < 2; half++) {
                int r = r0 + half*8;
                float v0 = acc[mt][nt][2*half] + bias[c0];
                float v1 = acc[mt][nt][2*half+1] + bias[c0+1];
                int b = r >> 11, s = r & (MHA_S-1);
                int h = c0 >> 6, dk = c0 & 63;
                if (z < 2) {
                    size_t idx = (((size_t)(b*MHA_H + h))*MHA_S + s)*MHA_DK + dk;
                    *(mha_h2*)(Ch + idx) = __floats2half2_rn(v0, v1);
                } else {
                    size_t idx = (((size_t)(b*MHA_H + h))*MHA_DK + dk)*MHA_S + s;
                    Ch[idx]         = __float2half_rn(v0);
                    Ch[idx + MHA_S] = __float2half_rn(v1);
                }
            }
        }
}

// output projection: fp32 + bias
__global__ void __launch_bounds__(256, 2) mha_gemm_out(
    const mha_h* __restrict__ Ah, const mha_h* __restrict__ Bh,
    const float* __restrict__ bias, float* __restrict__ Cf)
{
    extern __shared__ char smem[];
    uint32_t sbase = (uint32_t)__cvta_generic_to_shared(smem);
    int tid = threadIdx.x, warp = tid >> 5, lane = tid & 31;
    int bm = blockIdx.y * 128, bn = blockIdx.x * 128;

    float acc[4][4][4];
    mha_gemm_core(sbase, tid, warp, lane, bm, bn, Ah, Bh, acc);

    int wm = warp >> 2, wn = warp & 3;
    #pragma unroll
    for (int mt = 0; mt < 4; mt++)
        #pragma unroll
        for (int nt = 0; nt < 4; nt++) {
            int r0 = bm + wm*64 + mt*16 + (lane >> 2);
            int c0 = bn + wn*32 + nt*8  + (lane & 3)*2;
            #pragma unroll
            for (int half = 0; half < 2; half++) {
                int r = r0 + half*8;
                float2 o = make_float2(acc[mt][nt][2*half]   + bias[c0],
                                       acc[mt][nt][2*half+1] + bias[c0+1]);
                *(float2*)(Cf + (size_t)r*MHA_D + c0) = o;
            }
        }
}

// =================== flash attention, two kernels ============================
constexpr int FS_KB  = 128*128;               // K tile 16KB
constexpr int FS_VB  = 64*256;                // V tile 16KB
constexpr int FS1_SMEM = 2*FS_KB;             // pass1: 32KB -> 3 CTAs/SM
constexpr int FS2_STAGE = FS_KB + FS_VB;      // pass2 stage 32KB
constexpr int FS2_SMEM  = 2*FS2_STAGE;        // 64KB -> 2 CTAs/SM

__device__ __forceinline__ uint32_t fs_swzk(int row, int c) {
    return (uint32_t)(row*128 + ((c ^ (row & 7)) << 4));
}
__device__ __forceinline__ uint32_t fs_swzv(int row, int c) {
    return (uint32_t)(row*256 + ((c ^ (row & 7)) << 4));
}

__device__ __forceinline__ void fs_loadK(uint32_t sb, int tid, int bh, int t,
                                         const mha_h* Kh) {
    #pragma unroll
    for (int i = tid; i < 1024; i += 256) {
        int row = i >> 3, c = i & 7;
        size_t g = ((size_t)bh*MHA_S + t*128 + row)*MHA_DK + c*8;
        mha_cpa16(sb + fs_swzk(row, c), Kh + g);
    }
}
__device__ __forceinline__ void fs_loadV(uint32_t sb, int tid, int bh, int t,
                                         const mha_h* Vh) {
    #pragma unroll
    for (int i = tid; i < 1024; i += 256) {
        int row = i >> 4, c = i & 15;
        size_t g = ((size_t)bh*MHA_DK + row)*MHA_S + t*128 + c*8;
        mha_cpa16(sb + FS_KB + fs_swzv(row, c), Vh + g);
    }
}

// Q A-fragments loaded directly from gmem (no smem, no ldsm)
__device__ __forceinline__ void fs_loadQfrag(
    uint32_t qfh[4][4], const mha_h* Qh, int bh, int q0, int warp, int lane)
{
    int row = q0 + warp*16 + (lane >> 2);
    const mha_h* base = Qh + ((size_t)bh*MHA_S + row)*MHA_DK + (lane & 3)*2;
    #pragma unroll
    for (int j = 0; j < 4; j++) {
        qfh[j][0] = *(const uint32_t*)(base + j*16);
        qfh[j][1] = *(const uint32_t*)(base + j*16 + 8*MHA_DK);
        qfh[j][2] = *(const uint32_t*)(base + j*16 + 8);
        qfh[j][3] = *(const uint32_t*)(base + j*16 + 8*MHA_DK + 8);
    }
}

// hi-only 16x64 score half-tile, scaled by 1/8
__device__ __forceinline__ void fs_scores_hi(
    float acc[8][4], uint32_t kbase, int hf, int lane, const uint32_t qh[4][4])
{
    #pragma unroll
    for (int nt = 0; nt < 8; nt++)
        #pragma unroll
        for (int r = 0; r < 4; r++) acc[nt][r] = 0.f;
    #pragma unroll
    for (int j = 0; j < 4; j++) {
        uint32_t kh[8][2];
        #pragma unroll
        for (int g = 0; g < 4; g++) {
            int r = hf*64 + g*16 + (lane & 15);
            int c = 2*j + (lane >> 4);
            uint32_t t0,t1,t2,t3;
            mha_ldsm4(t0,t1,t2,t3, kbase + fs_swzk(r, c));
            kh[2*g][0]=t0; kh[2*g][1]=t2; kh[2*g+1][0]=t1; kh[2*g+1][1]=t3;
        }
        #pragma unroll
        for (int nt = 0; nt < 8; nt++)
            mha_mma(acc[nt], qh[j], kh[nt]);
    }
    #pragma unroll
    for (int nt = 0; nt < 8; nt++)
        #pragma unroll
        for (int r = 0; r < 4; r++) acc[nt][r] *= 0.125f;
}

// pass 1: row sums of exp(S) -> g_inv (3 CTAs/SM)
__global__ void __launch_bounds__(256, 3) mha_flash_p1(
    const mha_h* __restrict__ Qh, const mha_h* __restrict__ Kh,
    float* __restrict__ ginv)
{
    extern __shared__ char smem[];
    uint32_t stg = (uint32_t)__cvta_generic_to_shared(smem);

    int tid = threadIdx.x;
    int warp = tid >> 5, lane = tid & 31;
    int bh = blockIdx.y;
    int q0 = blockIdx.x * 128;

    uint32_t qfh[4][4];
    fs_loadQfrag(qfh, Qh, bh, q0, warp, lane);
    float s0 = 0.f, s1 = 0.f;

    fs_loadK(stg, tid, bh, 0, Kh);
    mha_cp_commit();

    for (int t = 0; t < 16; t++) {
        if (t + 1 < 16) fs_loadK(stg + ((t+1)&1)*FS_KB, tid, bh, t+1, Kh);
        mha_cp_commit();
        mha_cp_wait<1>(); __syncthreads();

        uint32_t kb = stg + (t&1)*FS_KB;
        #pragma unroll
        for (int hf = 0; hf < 2; hf++) {
            float acc[8][4];
            fs_scores_hi(acc, kb, hf, lane, qfh);
            #pragma unroll
            for (int nt = 0; nt < 8; nt++) {
                s0 += __expf(acc[nt][0]) + __expf(acc[nt][1]);
                s1 += __expf(acc[nt][2]) + __expf(acc[nt][3]);
            }
        }
        __syncthreads();
    }

    s0 += __shfl_xor_sync(0xffffffffu, s0, 1);
    s0 += __shfl_xor_sync(0xffffffffu, s0, 2);
    s1 += __shfl_xor_sync(0xffffffffu, s1, 1);
    s1 += __shfl_xor_sync(0xffffffffu, s1, 2);

    if ((lane & 3) == 0) {
        int row = q0 + warp*16 + (lane >> 2);
        ginv[(size_t)bh*MHA_S + row]     = 1.f / s0;
        ginv[(size_t)bh*MHA_S + row + 8] = 1.f / s1;
    }
}

// pass 2: P = exp(S)*inv, write P, O += P·Vh (2 CTAs/SM)
__global__ void __launch_bounds__(256, 2) mha_flash_p2(
    const mha_h* __restrict__ Qh, const mha_h* __restrict__ Kh,
    const mha_h* __restrict__ Vh, const float* __restrict__ ginv,
    float* __restrict__ attn, mha_h* __restrict__ Oh)
{
    extern __shared__ char smem[];
    uint32_t stg = (uint32_t)__cvta_generic_to_shared(smem);

    int tid = threadIdx.x;
    int warp = tid >> 5, lane = tid & 31;
    int bh = blockIdx.y;
    int q0 = blockIdx.x * 128;

    uint32_t qfh[4][4];
    fs_loadQfrag(qfh, Qh, bh, q0, warp, lane);

    int qrow0 = q0 + warp*16 + (lane >> 2);
    float inv0 = ginv[(size_t)bh*MHA_S + qrow0];
    float inv1 = ginv[(size_t)bh*MHA_S + qrow0 + 8];

    float oacc[8][4];
    #pragma unroll
    for (int nd = 0; nd < 8; nd++)
        #pragma unroll
        for (int r = 0; r < 4; r++) oacc[nd][r] = 0.f;

    fs_loadK(stg, tid, bh, 0, Kh);
    fs_loadV(stg, tid, bh, 0, Vh);
    mha_cp_commit();

    for (int t = 0; t < 16; t++) {
        if (t + 1 < 16) {
            fs_loadK(stg + ((t+1)&1)*FS2_STAGE, tid, bh, t+1, Kh);
            fs_loadV(stg + ((t+1)&1)*FS2_STAGE, tid, bh, t+1, Vh);
        }
        mha_cp_commit();
        mha_cp_wait<1>(); __syncthreads();

        uint32_t kb = stg + (t&1)*FS2_STAGE;
        #pragma unroll
        for (int hf = 0; hf < 2; hf++) {
            float acc[8][4];
            fs_scores_hi(acc, kb, hf, lane, qfh);
            #pragma unroll
            for (int nt = 0; nt < 8; nt++) {
                acc[nt][0] = __expf(acc[nt][0])*inv0;
                acc[nt][1] = __expf(acc[nt][1])*inv0;
                acc[nt][2] = __expf(acc[nt][2])*inv1;
                acc[nt][3] = __expf(acc[nt][3])*inv1;
            }
            {
                size_t rb0 = ((size_t)bh*MHA_S + qrow0)    *MHA_S + t*128 + hf*64 + (lane&3)*2;
                size_t rb1 = ((size_t)bh*MHA_S + qrow0 + 8)*MHA_S + t*128 + hf*64 + (lane&3)*2;
                #pragma unroll
                for (int nt = 0; nt < 8; nt++) {
                    *(float2*)(attn + rb0 + nt*8) = make_float2(acc[nt][0], acc[nt][1]);
                    *(float2*)(attn + rb1 + nt*8) = make_float2(acc[nt][2], acc[nt][3]);
                }
            }
            #pragma unroll
            for (int kk = 0; kk < 4; kk++) {
                uint32_t pah[4];
                pah[0] = mha_pack(acc[2*kk][0],   acc[2*kk][1]);
                pah[1] = mha_pack(acc[2*kk][2],   acc[2*kk][3]);
                pah[2] = mha_pack(acc[2*kk+1][0], acc[2*kk+1][1]);
                pah[3] = mha_pack(acc[2*kk+1][2], acc[2*kk+1][3]);

                uint32_t vbh[8][2];
                #pragma unroll
                for (int g = 0; g < 4; g++) {
                    int r = g*16 + (lane & 15);
                    int c = 2*(hf*4 + kk) + (lane >> 4);
                    uint32_t t0,t1,t2,t3;
                    mha_ldsm4(t0,t1,t2,t3, kb + FS_KB + fs_swzv(r, c));
                    vbh[2*g][0]=t0; vbh[2*g][1]=t2; vbh[2*g+1][0]=t1; vbh[2*g+1][1]=t3;
                }
                #pragma unroll
                for (int nd = 0; nd < 8; nd++)
                    mha_mma(oacc[nd], pah, vbh[nd]);
            }
        }
        __syncthreads();
    }

    int b = bh >> 4, h = bh & 15;
    #pragma unroll
    for (int nd = 0; nd < 8; nd++) {
        int dk = nd*8 + (lane & 3)*2;
        size_t i0 = ((size_t)(b*MHA_S + qrow0))    *MHA_D + h*MHA_DK + dk;
        size_t i1 = ((size_t)(b*MHA_S + qrow0 + 8))*MHA_D + h*MHA_DK + dk;
        *(mha_h2*)(Oh + i0) = __floats2half2_rn(oacc[nd][0], oacc[nd][1]);
        *(mha_h2*)(Oh + i1) = __floats2half2_rn(oacc[nd][2], oacc[nd][3]);
    }
}

// ---------------- host ----------------
extern "C" void kernel_launch(void* const* d_in, const int* in_sizes, int n_in,
                              void* d_out, int out_size)
{
    (void)in_sizes; (void)n_in; (void)out_size;
    const float* q  = (const float*)d_in[0];
    const float* k  = (const float*)d_in[1];
    const float* v  = (const float*)d_in[2];
    const float* wq = (const float*)d_in[3];
    const float* bq = (const float*)d_in[4];
    const float* wk = (const float*)d_in[5];
    const float* bk = (const float*)d_in[6];
    const float* wv = (const float*)d_in[7];
    const float* bv = (const float*)d_in[8];
    const float* wo = (const float*)d_in[9];
    const float* bo = (const float*)d_in[10];

    float* out  = (float*)d_out;
    float* attn = out + (size_t)MHA_B * MHA_S * MHA_D;

    mha_h *inh, *wh, *Qh, *Kh, *Vth, *Oh;
    float *ginv;
    cudaGetSymbolAddress((void**)&inh,  g_inh);
    cudaGetSymbolAddress((void**)&wh,   g_wh);
    cudaGetSymbolAddress((void**)&Qh,   g_Qh);
    cudaGetSymbolAddress((void**)&Kh,   g_Kh);
    cudaGetSymbolAddress((void**)&Vth,  g_Vth);
    cudaGetSymbolAddress((void**)&Oh,   g_Oh);
    cudaGetSymbolAddress((void**)&ginv, g_inv);

    const size_t NIN = (size_t)8192*1024;
    const size_t NW  = (size_t)1024*1024;

    mha_split_in3<<<dim3((unsigned)(NIN/4/256), 3), 256>>>(q, k, v, inh);
    mha_split_w4h<<<dim3((unsigned)(NW/4/256),  4), 256>>>(wq, wk, wv, wo, wh);

    const int SMG = 2 * (128*64 + 128*64);   // 32768 B
    cudaFuncSetAttribute(mha_gemm_qkv, cudaFuncAttributeMaxDynamicSharedMemorySize, SMG);
    cudaFuncSetAttribute(mha_gemm_out, cudaFuncAttributeMaxDynamicSharedMemorySize, SMG);
    cudaFuncSetAttribute(mha_flash_p1, cudaFuncAttributeMaxDynamicSharedMemorySize, FS1_SMEM);
    cudaFuncSetAttribute(mha_flash_p2, cudaFuncAttributeMaxDynamicSharedMemorySize, FS2_SMEM);

    dim3 t(256);

    // merged Q/K/V projections: one launch, 1536 CTAs
    mha_gemm_qkv<<<dim3(8, 64, 3), t, SMG>>>(inh, wh, bq, bk, bv, Qh, Kh, Vth);

    // flash: pass 1 (sums) then pass 2 (P + PV)
    dim3 gf(16, MHA_B*MHA_H);
    mha_flash_p1<<<gf, t, FS1_SMEM>>>(Qh, Kh, ginv);
    mha_flash_p2<<<gf, t, FS2_SMEM>>>(Qh, Kh, Vth, ginv, attn, Oh);

    // output projection
    mha_gemm_out<<<dim3(8, 64), t, SMG>>>(Oh, wh + 3*NW, bo, out);
}

// round 16
// speedup vs baseline: 1.9752x; 1.0515x over previous
#include <cuda_runtime.h>
#include <cuda_fp16.h>
#include <cstdint>
#include <cstddef>

typedef __half  mha_h;
typedef __half2 mha_h2;

constexpr int MHA_B  = 4;
constexpr int MHA_S  = 2048;
constexpr int MHA_D  = 1024;
constexpr int MHA_H  = 16;
constexpr int MHA_DK = 64;

// softmax scale folded into Q: exp(q.k/8) == exp2((q*QSCALE).k)
constexpr float MHA_QSCALE = 0.18033688011112042f;   // 0.125 * log2(e)

// ---------------- scratch ----------------
__device__ mha_h g_inh[(size_t)3*8192*1024];                     // input hi
__device__ mha_h g_wh [(size_t)4*1024*1024];                     // weight hi
__device__ mha_h g_Qh[(size_t)8388608];                          // [bh][s][dk] pre-scaled
__device__ mha_h g_Kh[(size_t)8388608];                          // [bh][s][dk]
__device__ mha_h g_Vth[(size_t)8388608];                         // [bh][dk][s]
__device__ mha_h g_Oh[(size_t)8388608];                          // [b][s][d]
__device__ float g_inv[(size_t)64*2048];                         // 1/rowsum

// ---------------- PTX helpers ----------------
__device__ __forceinline__ void mha_cpa16(uint32_t dst, const void* src) {
    asm volatile("cp.async.cg.shared.global [%0], [%1], 16;\n" :: "r"(dst), "l"(src));
}
__device__ __forceinline__ void mha_cp_commit() { asm volatile("cp.async.commit_group;\n"); }
template<int N> __device__ __forceinline__ void mha_cp_wait() {
    asm volatile("cp.async.wait_group %0;\n" :: "n"(N));
}
__device__ __forceinline__ void mha_ldsm4(uint32_t &r0, uint32_t &r1, uint32_t &r2,
                                          uint32_t &r3, uint32_t addr) {
    asm volatile("ldmatrix.sync.aligned.m8n8.x4.shared.b16 {%0,%1,%2,%3}, [%4];\n"
        : "=r"(r0),"=r"(r1),"=r"(r2),"=r"(r3) : "r"(addr));
}
__device__ __forceinline__ void mha_mma(float* d, const uint32_t* a, const uint32_t* b) {
    asm volatile("mma.sync.aligned.m16n8k16.row.col.f32.f16.f16.f32 "
      "{%0,%1,%2,%3}, {%4,%5,%6,%7}, {%8,%9}, {%0,%1,%2,%3};\n"
      : "+f"(d[0]),"+f"(d[1]),"+f"(d[2]),"+f"(d[3])
      : "r"(a[0]),"r"(a[1]),"r"(a[2]),"r"(a[3]),"r"(b[0]),"r"(b[1]));
}
__device__ __forceinline__ uint32_t mha_pack(float a, float b) {
    mha_h2 t = __floats2half2_rn(a, b);
    return *(uint32_t*)&t;
}
__device__ __forceinline__ float mha_ex2(float x) {
    float r;
    asm("ex2.approx.ftz.f32 %0, %1;" : "=f"(r) : "f"(x));
    return r;
}

// ---------------- input/weight split (hi only) ----------------
__global__ void mha_split_in3(const float* __restrict__ q, const float* __restrict__ k,
                              const float* __restrict__ v, mha_h* __restrict__ h) {
    const size_t NIN = (size_t)8192*1024;
    int seg = blockIdx.y;
    const float* x = (seg == 0) ? q : (seg == 1) ? k : v;
    size_t i = (size_t)blockIdx.x*blockDim.x + threadIdx.x;
    if (i >= NIN/4) return;
    float4 val = ((const float4*)x)[i];
    size_t o = (size_t)seg*(NIN/2) + 2*i;
    ((mha_h2*)h)[o]   = __floats2half2_rn(val.x, val.y);
    ((mha_h2*)h)[o+1] = __floats2half2_rn(val.z, val.w);
}
__global__ void mha_split_w4h(const float* __restrict__ wq, const float* __restrict__ wk,
                              const float* __restrict__ wv, const float* __restrict__ wo,
                              mha_h* __restrict__ h) {
    const size_t NW = (size_t)1024*1024;
    int seg = blockIdx.y;
    const float* x = (seg == 0) ? wq : (seg == 1) ? wk : (seg == 2) ? wv : wo;
    size_t i = (size_t)blockIdx.x*blockDim.x + threadIdx.x;
    if (i >= NW/4) return;
    float4 val = ((const float4*)x)[i];
    size_t o = (size_t)seg*(NW/2) + 2*i;
    ((mha_h2*)h)[o]   = __floats2half2_rn(val.x, val.y);
    ((mha_h2*)h)[o+1] = __floats2half2_rn(val.z, val.w);
}

// ---------------- projection GEMM core pieces ----------------
__device__ __forceinline__ uint32_t mha_swz(int row, int kc) {
    return (uint32_t)(row*64 + ((kc ^ ((row >> 1) & 3)) << 4));
}

__device__ __forceinline__ void mha_issue(
    uint32_t s0, int tid, int bm, int bn, int kk,
    const mha_h* pAh, const mha_h* pBh)
{
    constexpr int K = 1024;
    constexpr int ABYTES = 128 * 64;
    #pragma unroll
    for (int c = tid; c < 512; c += 256) {
        int row = c >> 2, kc = c & 3;
        uint32_t off = mha_swz(row, kc);
        size_t g = (size_t)(bm + row) * K + kk + kc*8;
        mha_cpa16(s0 + off, pAh + g);
    }
    #pragma unroll
    for (int c = tid; c < 512; c += 256) {
        int row = c >> 2, kc = c & 3;
        uint32_t off = mha_swz(row, kc);
        size_t g = (size_t)(bn + row) * K + kk + kc*8;
        mha_cpa16(s0 + ABYTES + off, pBh + g);
    }
}

__device__ __forceinline__ void mha_gemm_core(
    uint32_t sbase, int tid, int warp, int lane, int bm, int bn,
    const mha_h* Ah, const mha_h* Bh, float acc[4][4][4])
{
    constexpr int ABYTES = 128 * 64;
    constexpr int STAGE  = 2 * ABYTES;
    int wm = warp >> 2, wn = warp & 3;

    #pragma unroll
    for (int i = 0; i < 4; i++)
        #pragma unroll
        for (int j = 0; j < 4; j++)
            #pragma unroll
            for (int r = 0; r < 4; r++) acc[i][j][r] = 0.f;

    mha_issue(sbase, tid, bm, bn, 0, Ah, Bh);
    mha_cp_commit();

    for (int it = 0; it < 32; it++) {
        if (it + 1 < 32)
            mha_issue(sbase + ((it+1)&1)*STAGE, tid, bm, bn, (it+1)*32, Ah, Bh);
        mha_cp_commit();
        mha_cp_wait<1>(); __syncthreads();

        uint32_t sAh0 = sbase + (it&1)*STAGE;
        uint32_t sBh0 = sAh0 + ABYTES;

        #pragma unroll
        for (int ks = 0; ks < 2; ks++) {
            int kc0 = ks * 2;
            uint32_t fah[4][4], fbh[4][2];
            #pragma unroll
            for (int mt = 0; mt < 4; mt++) {
                int r  = wm*64 + mt*16 + (lane & 15);
                int kc = kc0 + (lane >> 4);
                mha_ldsm4(fah[mt][0],fah[mt][1],fah[mt][2],fah[mt][3],
                          sAh0 + mha_swz(r, kc));
            }
            #pragma unroll
            for (int g = 0; g < 2; g++) {
                int r  = wn*32 + g*16 + (lane & 15);
                int kc = kc0 + (lane >> 4);
                uint32_t t0,t1,t2,t3;
                mha_ldsm4(t0,t1,t2,t3, sBh0 + mha_swz(r, kc));
                fbh[2*g][0]=t0; fbh[2*g][1]=t2; fbh[2*g+1][0]=t1; fbh[2*g+1][1]=t3;
            }
            #pragma unroll
            for (int mt = 0; mt < 4; mt++)
                #pragma unroll
                for (int nt = 0; nt < 4; nt++)
                    mha_mma(acc[mt][nt], fah[mt], fbh[nt]);
        }
        __syncthreads();
    }
}

// merged Q/K/V projection; Q epilogue pre-scales by MHA_QSCALE
__global__ void __launch_bounds__(256, 2) mha_gemm_qkv(
    const mha_h* __restrict__ inh, const mha_h* __restrict__ wh,
    const float* __restrict__ bq, const float* __restrict__ bk,
    const float* __restrict__ bv,
    mha_h* __restrict__ Qh, mha_h* __restrict__ Kh, mha_h* __restrict__ Vth)
{
    extern __shared__ char smem[];
    uint32_t sbase = (uint32_t)__cvta_generic_to_shared(smem);
    int tid = threadIdx.x, warp = tid >> 5, lane = tid & 31;
    int bm = blockIdx.y * 128, bn = blockIdx.x * 128;
    int z = blockIdx.z;

    const size_t NIN = (size_t)8192*1024;
    const size_t NW  = (size_t)1024*1024;
    const mha_h* Ah = inh + (size_t)z*NIN;
    const mha_h* Bh = wh  + (size_t)z*NW;
    const float* bias = (z == 0) ? bq : (z == 1) ? bk : bv;
    mha_h* Ch = (z == 0) ? Qh : (z == 1) ? Kh : Vth;
    float oscale = (z == 0) ? MHA_QSCALE : 1.f;

    float acc[4][4][4];
    mha_gemm_core(sbase, tid, warp, lane, bm, bn, Ah, Bh, acc);

    int wm = warp >> 2, wn = warp & 3;
    #pragma unroll
    for (int mt = 0; mt < 4; mt++)
        #pragma unroll
        for (int nt = 0; nt < 4; nt++) {
            int r0 = bm + wm*64 + mt*16 + (lane >> 2);
            int c0 = bn + wn*32 + nt*8  + (lane & 3)*2;
            #pragma unroll
            for (int half = 0; half < 2; half++) {
                int r = r0 + half*8;
                float v0 = (acc[mt][nt][2*half]   + bias[c0])   * oscale;
                float v1 = (acc[mt][nt][2*half+1] + bias[c0+1]) * oscale;
                int b = r >> 11, s = r & (MHA_S-1);
                int h = c0 >> 6, dk = c0 & 63;
                if (z < 2) {
                    size_t idx = (((size_t)(b*MHA_H + h))*MHA_S + s)*MHA_DK + dk;
                    *(mha_h2*)(Ch + idx) = __floats2half2_rn(v0, v1);
                } else {
                    size_t idx = (((size_t)(b*MHA_H + h))*MHA_DK + dk)*MHA_S + s;
                    Ch[idx]         = __float2half_rn(v0);
                    Ch[idx + MHA_S] = __float2half_rn(v1);
                }
            }
        }
}

// output projection: fp32 + bias
__global__ void __launch_bounds__(256, 2) mha_gemm_out(
    const mha_h* __restrict__ Ah, const mha_h* __restrict__ Bh,
    const float* __restrict__ bias, float* __restrict__ Cf)
{
    extern __shared__ char smem[];
    uint32_t sbase = (uint32_t)__cvta_generic_to_shared(smem);
    int tid = threadIdx.x, warp = tid >> 5, lane = tid & 31;
    int bm = blockIdx.y * 128, bn = blockIdx.x * 128;

    float acc[4][4][4];
    mha_gemm_core(sbase, tid, warp, lane, bm, bn, Ah, Bh, acc);

    int wm = warp >> 2, wn = warp & 3;
    #pragma unroll
    for (int mt = 0; mt < 4; mt++)
        #pragma unroll
        for (int nt = 0; nt < 4; nt++) {
            int r0 = bm + wm*64 + mt*16 + (lane >> 2);
            int c0 = bn + wn*32 + nt*8  + (lane & 3)*2;
            #pragma unroll
            for (int half = 0; half < 2; half++) {
                int r = r0 + half*8;
                float2 o = make_float2(acc[mt][nt][2*half]   + bias[c0],
                                       acc[mt][nt][2*half+1] + bias[c0+1]);
                *(float2*)(Cf + (size_t)r*MHA_D + c0) = o;
            }
        }
}

// =================== flash attention, two kernels ============================
constexpr int FS_KB  = 128*128;
constexpr int FS_VB  = 64*256;
constexpr int FS1_SMEM = 2*FS_KB;             // 32KB -> 3 CTAs/SM
constexpr int FS2_STAGE = FS_KB + FS_VB;      // 32KB
constexpr int FS2_SMEM  = 2*FS2_STAGE;        // 64KB -> 2 CTAs/SM

__device__ __forceinline__ uint32_t fs_swzk(int row, int c) {
    return (uint32_t)(row*128 + ((c ^ (row & 7)) << 4));
}
__device__ __forceinline__ uint32_t fs_swzv(int row, int c) {
    return (uint32_t)(row*256 + ((c ^ (row & 7)) << 4));
}

__device__ __forceinline__ void fs_loadK(uint32_t sb, int tid, int bh, int t,
                                         const mha_h* Kh) {
    #pragma unroll
    for (int i = tid; i < 1024; i += 256) {
        int row = i >> 3, c = i & 7;
        size_t g = ((size_t)bh*MHA_S + t*128 + row)*MHA_DK + c*8;
        mha_cpa16(sb + fs_swzk(row, c), Kh + g);
    }
}
__device__ __forceinline__ void fs_loadV(uint32_t sb, int tid, int bh, int t,
                                         const mha_h* Vh) {
    #pragma unroll
    for (int i = tid; i < 1024; i += 256) {
        int row = i >> 4, c = i & 15;
        size_t g = ((size_t)bh*MHA_DK + row)*MHA_S + t*128 + c*8;
        mha_cpa16(sb + FS_KB + fs_swzv(row, c), Vh + g);
    }
}

__device__ __forceinline__ void fs_loadQfrag(
    uint32_t qfh[4][4], const mha_h* Qh, int bh, int q0, int warp, int lane)
{
    int row = q0 + warp*16 + (lane >> 2);
    const mha_h* base = Qh + ((size_t)bh*MHA_S + row)*MHA_DK + (lane & 3)*2;
    #pragma unroll
    for (int j = 0; j < 4; j++) {
        qfh[j][0] = *(const uint32_t*)(base + j*16);
        qfh[j][1] = *(const uint32_t*)(base + j*16 + 8*MHA_DK);
        qfh[j][2] = *(const uint32_t*)(base + j*16 + 8);
        qfh[j][3] = *(const uint32_t*)(base + j*16 + 8*MHA_DK + 8);
    }
}

// 16x64 score half-tile (Q pre-scaled; result feeds ex2 directly)
__device__ __forceinline__ void fs_scores_hi(
    float acc[8][4], uint32_t kbase, int hf, int lane, const uint32_t qh[4][4])
{
    #pragma unroll
    for (int nt = 0; nt < 8; nt++)
        #pragma unroll
        for (int r = 0; r < 4; r++) acc[nt][r] = 0.f;
    #pragma unroll
    for (int j = 0; j < 4; j++) {
        uint32_t kh[8][2];
        #pragma unroll
        for (int g = 0; g < 4; g++) {
            int r = hf*64 + g*16 + (lane & 15);
            int c = 2*j + (lane >> 4);
            uint32_t t0,t1,t2,t3;
            mha_ldsm4(t0,t1,t2,t3, kbase + fs_swzk(r, c));
            kh[2*g][0]=t0; kh[2*g][1]=t2; kh[2*g+1][0]=t1; kh[2*g+1][1]=t3;
        }
        #pragma unroll
        for (int nt = 0; nt < 8; nt++)
            mha_mma(acc[nt], qh[j], kh[nt]);
    }
}

// pass 1: row sums of exp2(S') -> g_inv (3 CTAs/SM)
__global__ void __launch_bounds__(256, 3) mha_flash_p1(
    const mha_h* __restrict__ Qh, const mha_h* __restrict__ Kh,
    float* __restrict__ ginv)
{
    extern __shared__ char smem[];
    uint32_t stg = (uint32_t)__cvta_generic_to_shared(smem);

    int tid = threadIdx.x;
    int warp = tid >> 5, lane = tid & 31;
    int bh = blockIdx.y;
    int q0 = blockIdx.x * 128;

    uint32_t qfh[4][4];
    fs_loadQfrag(qfh, Qh, bh, q0, warp, lane);
    float s0 = 0.f, s1 = 0.f;

    fs_loadK(stg, tid, bh, 0, Kh);
    mha_cp_commit();

    for (int t = 0; t < 16; t++) {
        if (t + 1 < 16) fs_loadK(stg + ((t+1)&1)*FS_KB, tid, bh, t+1, Kh);
        mha_cp_commit();
        mha_cp_wait<1>(); __syncthreads();

        uint32_t kb = stg + (t&1)*FS_KB;
        #pragma unroll
        for (int hf = 0; hf < 2; hf++) {
            float acc[8][4];
            fs_scores_hi(acc, kb, hf, lane, qfh);
            #pragma unroll
            for (int nt = 0; nt < 8; nt++) {
                s0 += mha_ex2(acc[nt][0]) + mha_ex2(acc[nt][1]);
                s1 += mha_ex2(acc[nt][2]) + mha_ex2(acc[nt][3]);
            }
        }
        __syncthreads();
    }

    s0 += __shfl_xor_sync(0xffffffffu, s0, 1);
    s0 += __shfl_xor_sync(0xffffffffu, s0, 2);
    s1 += __shfl_xor_sync(0xffffffffu, s1, 1);
    s1 += __shfl_xor_sync(0xffffffffu, s1, 2);

    if ((lane & 3) == 0) {
        int row = q0 + warp*16 + (lane >> 2);
        ginv[(size_t)bh*MHA_S + row]     = 1.f / s0;
        ginv[(size_t)bh*MHA_S + row + 8] = 1.f / s1;
    }
}

// pass 2: P = exp2(S')*inv, write P, O += P·Vh (2 CTAs/SM)
__global__ void __launch_bounds__(256, 2) mha_flash_p2(
    const mha_h* __restrict__ Qh, const mha_h* __restrict__ Kh,
    const mha_h* __restrict__ Vh, const float* __restrict__ ginv,
    float* __restrict__ attn, mha_h* __restrict__ Oh)
{
    extern __shared__ char smem[];
    uint32_t stg = (uint32_t)__cvta_generic_to_shared(smem);

    int tid = threadIdx.x;
    int warp = tid >> 5, lane = tid & 31;
    int bh = blockIdx.y;
    int q0 = blockIdx.x * 128;

    uint32_t qfh[4][4];
    fs_loadQfrag(qfh, Qh, bh, q0, warp, lane);

    int qrow0 = q0 + warp*16 + (lane >> 2);
    float inv0 = ginv[(size_t)bh*MHA_S + qrow0];
    float inv1 = ginv[(size_t)bh*MHA_S + qrow0 + 8];

    float oacc[8][4];
    #pragma unroll
    for (int nd = 0; nd < 8; nd++)
        #pragma unroll
        for (int r = 0; r < 4; r++) oacc[nd][r] = 0.f;

    fs_loadK(stg, tid, bh, 0, Kh);
    fs_loadV(stg, tid, bh, 0, Vh);
    mha_cp_commit();

    for (int t = 0; t < 16; t++) {
        if (t + 1 < 16) {
            fs_loadK(stg + ((t+1)&1)*FS2_STAGE, tid, bh, t+1, Kh);
            fs_loadV(stg + ((t+1)&1)*FS2_STAGE, tid, bh, t+1, Vh);
        }
        mha_cp_commit();
        mha_cp_wait<1>(); __syncthreads();

        uint32_t kb = stg + (t&1)*FS2_STAGE;
        #pragma unroll
        for (int hf = 0; hf < 2; hf++) {
            float acc[8][4];
            fs_scores_hi(acc, kb, hf, lane, qfh);
            #pragma unroll
            for (int nt = 0; nt < 8; nt++) {
                acc[nt][0] = mha_ex2(acc[nt][0])*inv0;
                acc[nt][1] = mha_ex2(acc[nt][1])*inv0;
                acc[nt][2] = mha_ex2(acc[nt][2])*inv1;
                acc[nt][3] = mha_ex2(acc[nt][3])*inv1;
            }
            {
                size_t rb0 = ((size_t)bh*MHA_S + qrow0)    *MHA_S + t*128 + hf*64 + (lane&3)*2;
                size_t rb1 = ((size_t)bh*MHA_S + qrow0 + 8)*MHA_S + t*128 + hf*64 + (lane&3)*2;
                #pragma unroll
                for (int nt = 0; nt < 8; nt++) {
                    *(float2*)(attn + rb0 + nt*8) = make_float2(acc[nt][0], acc[nt][1]);
                    *(float2*)(attn + rb1 + nt*8) = make_float2(acc[nt][2], acc[nt][3]);
                }
            }
            #pragma unroll
            for (int kk = 0; kk < 4; kk++) {
                uint32_t pah[4];
                pah[0] = mha_pack(acc[2*kk][0],   acc[2*kk][1]);
                pah[1] = mha_pack(acc[2*kk][2],   acc[2*kk][3]);
                pah[2] = mha_pack(acc[2*kk+1][0], acc[2*kk+1][1]);
                pah[3] = mha_pack(acc[2*kk+1][2], acc[2*kk+1][3]);

                uint32_t vbh[8][2];
                #pragma unroll
                for (int g = 0; g < 4; g++) {
                    int r = g*16 + (lane & 15);
                    int c = 2*(hf*4 + kk) + (lane >> 4);
                    uint32_t t0,t1,t2,t3;
                    mha_ldsm4(t0,t1,t2,t3, kb + FS_KB + fs_swzv(r, c));
                    vbh[2*g][0]=t0; vbh[2*g][1]=t2; vbh[2*g+1][0]=t1; vbh[2*g+1][1]=t3;
                }
                #pragma unroll
                for (int nd = 0; nd < 8; nd++)
                    mha_mma(oacc[nd], pah, vbh[nd]);
            }
        }
        __syncthreads();
    }

    int b = bh >> 4, h = bh & 15;
    #pragma unroll
    for (int nd = 0; nd < 8; nd++) {
        int dk = nd*8 + (lane & 3)*2;
        size_t i0 = ((size_t)(b*MHA_S + qrow0))    *MHA_D + h*MHA_DK + dk;
        size_t i1 = ((size_t)(b*MHA_S + qrow0 + 8))*MHA_D + h*MHA_DK + dk;
        *(mha_h2*)(Oh + i0) = __floats2half2_rn(oacc[nd][0], oacc[nd][1]);
        *(mha_h2*)(Oh + i1) = __floats2half2_rn(oacc[nd][2], oacc[nd][3]);
    }
}

// ---------------- host ----------------
extern "C" void kernel_launch(void* const* d_in, const int* in_sizes, int n_in,
                              void* d_out, int out_size)
{
    (void)in_sizes; (void)n_in; (void)out_size;
    const float* q  = (const float*)d_in[0];
    const float* k  = (const float*)d_in[1];
    const float* v  = (const float*)d_in[2];
    const float* wq = (const float*)d_in[3];
    const float* bq = (const float*)d_in[4];
    const float* wk = (const float*)d_in[5];
    const float* bk = (const float*)d_in[6];
    const float* wv = (const float*)d_in[7];
    const float* bv = (const float*)d_in[8];
    const float* wo = (const float*)d_in[9];
    const float* bo = (const float*)d_in[10];

    float* out  = (float*)d_out;
    float* attn = out + (size_t)MHA_B * MHA_S * MHA_D;

    mha_h *inh, *wh, *Qh, *Kh, *Vth, *Oh;
    float *ginv;
    cudaGetSymbolAddress((void**)&inh,  g_inh);
    cudaGetSymbolAddress((void**)&wh,   g_wh);
    cudaGetSymbolAddress((void**)&Qh,   g_Qh);
    cudaGetSymbolAddress((void**)&Kh,   g_Kh);
    cudaGetSymbolAddress((void**)&Vth,  g_Vth);
    cudaGetSymbolAddress((void**)&Oh,   g_Oh);
    cudaGetSymbolAddress((void**)&ginv, g_inv);

    const size_t NIN = (size_t)8192*1024;
    const size_t NW  = (size_t)1024*1024;

    mha_split_in3<<<dim3((unsigned)(NIN/4/256), 3), 256>>>(q, k, v, inh);
    mha_split_w4h<<<dim3((unsigned)(NW/4/256),  4), 256>>>(wq, wk, wv, wo, wh);

    const int SMG = 2 * (128*64 + 128*64);
    cudaFuncSetAttribute(mha_gemm_qkv, cudaFuncAttributeMaxDynamicSharedMemorySize, SMG);
    cudaFuncSetAttribute(mha_gemm_out, cudaFuncAttributeMaxDynamicSharedMemorySize, SMG);
    cudaFuncSetAttribute(mha_flash_p1, cudaFuncAttributeMaxDynamicSharedMemorySize, FS1_SMEM);
    cudaFuncSetAttribute(mha_flash_p2, cudaFuncAttributeMaxDynamicSharedMemorySize, FS2_SMEM);

    dim3 t(256);

    mha_gemm_qkv<<<dim3(8, 64, 3), t, SMG>>>(inh, wh, bq, bk, bv, Qh, Kh, Vth);

    dim3 gf(16, MHA_B*MHA_H);
    mha_flash_p1<<<gf, t, FS1_SMEM>>>(Qh, Kh, ginv);
    mha_flash_p2<<<gf, t, FS2_SMEM>>>(Qh, Kh, Vth, ginv, attn, Oh);

    mha_gemm_out<<<dim3(8, 64), t, SMG>>>(Oh, wh + 3*NW, bo, out);
}